// round 13
// baseline (speedup 1.0000x reference)
#include <cuda_runtime.h>
#include <cuda_fp16.h>
#include <math.h>
#include <stdint.h>

#define BB 4
#define NQ 2048
#define FF 1024
#define CFF 768
#define HH 8
#define DD 64
#define MIDW 512
#define ROWS (BB*NQ)        // 8192
#define CROWS (BB*512)      // 2048
#define QK_SCALE (0.125f * 1.4426950408889634f)

// Scratch (device globals, fp16 activations)
__device__ __half g_xn[ROWS*FF];
__device__ __half g_cx[CROWS*CFF];
__device__ __half g_q [ROWS*MIDW];
__device__ __half g_kv[ROWS*2*MIDW];
__device__ __half g_ao[ROWS*MIDW];
__device__ __half g_wt[4*1024*1024];
__device__ float  g_nb[4096];          // folded LN-bias column vectors

#define OFF_SA_WQ  0                   // rows 0-511   of merged sa B (N=1536)
#define OFF_SA_WKV 524288              // rows 512-1535
#define OFF_SA_WO  1572864
#define OFF_CA_WQ  2097152
#define OFF_CA_WKV 2621440
#define OFF_CA_WO  3407872
#define NB_SA   0                      // 1536 entries (q:0-511, kv:512-1535)
#define NB_CA_Q 2048                   // 512
#define NB_CA_KV 2560                  // 1024

// ---------------------------------------------------------------------------
// helpers
// ---------------------------------------------------------------------------
__device__ __forceinline__ void cp16(void* dst, const void* src) {
    uint32_t d = (uint32_t)__cvta_generic_to_shared(dst);
    asm volatile("cp.async.cg.shared.global [%0], [%1], 16;\n" :: "r"(d), "l"(src));
}
__device__ __forceinline__ void cp_commit() { asm volatile("cp.async.commit_group;\n" ::: "memory"); }
__device__ __forceinline__ void cp_wait0()  { asm volatile("cp.async.wait_group 0;\n" ::: "memory"); }
__device__ __forceinline__ void cp_wait1()  { asm volatile("cp.async.wait_group 1;\n" ::: "memory"); }

__device__ __forceinline__ void mma16(float (&d)[4], const uint32_t (&a)[4],
                                      const uint32_t (&b)[2]) {
    asm volatile(
        "mma.sync.aligned.m16n8k16.row.col.f32.f16.f16.f32 "
        "{%0,%1,%2,%3},{%4,%5,%6,%7},{%8,%9},{%0,%1,%2,%3};\n"
        : "+f"(d[0]), "+f"(d[1]), "+f"(d[2]), "+f"(d[3])
        : "r"(a[0]), "r"(a[1]), "r"(a[2]), "r"(a[3]), "r"(b[0]), "r"(b[1]));
}
__device__ __forceinline__ uint32_t packh(float lo, float hi) {
    uint32_t r;
    asm("cvt.rn.f16x2.f32 %0, %1, %2;\n" : "=r"(r) : "f"(hi), "f"(lo));
    return r;
}
__device__ __forceinline__ float ex2f(float x) {
    float y; asm("ex2.approx.f32 %0, %1;\n" : "=f"(y) : "f"(x)); return y;
}
__device__ __forceinline__ void ldsm_x4(uint32_t (&r)[4], const void* p) {
    uint32_t a = (uint32_t)__cvta_generic_to_shared(p);
    asm volatile("ldmatrix.sync.aligned.m8n8.x4.shared.b16 {%0,%1,%2,%3}, [%4];\n"
                 : "=r"(r[0]), "=r"(r[1]), "=r"(r[2]), "=r"(r[3]) : "r"(a));
}
__device__ __forceinline__ void ldsm_x4_trans(uint32_t (&r)[4], const void* p) {
    uint32_t a = (uint32_t)__cvta_generic_to_shared(p);
    asm volatile("ldmatrix.sync.aligned.m8n8.x4.trans.shared.b16 {%0,%1,%2,%3}, [%4];\n"
                 : "=r"(r[0]), "=r"(r[1]), "=r"(r[2]), "=r"(r[3]) : "r"(a));
}

// ---------------------------------------------------------------------------
// Weight transpose + gain-fold + scale: fp32 [K][N] -> fp16 [N][K]
// out[n][k] = in[k][n] * (gain ? gain[k] : 1) * scale
// ---------------------------------------------------------------------------
__global__ void wtrans_kernel(const float* __restrict__ in, __half* __restrict__ out,
                              int K, int N, const float* __restrict__ gain, float scale) {
    __shared__ float t[32][33];
    int n0 = blockIdx.x * 32, k0 = blockIdx.y * 32;
    int tx = threadIdx.x, ty = threadIdx.y;
    #pragma unroll
    for (int i = 0; i < 4; i++)
        t[ty + i * 8][tx] = in[(size_t)(k0 + ty + i * 8) * N + n0 + tx];
    __syncthreads();
    float gk = (gain ? gain[k0 + tx] : 1.f) * scale;
    #pragma unroll
    for (int i = 0; i < 4; i++)
        out[(size_t)(n0 + ty + i * 8) * K + k0 + tx] = __float2half(t[tx][ty + i * 8] * gk);
}

// bias vector: out[n] = scale * sum_k b[k] * w[k][n]
__global__ void bvec_kernel(const float* __restrict__ b, const float* __restrict__ w,
                            float* __restrict__ out, int K, int N, float scale) {
    int n = blockIdx.x * 256 + threadIdx.x;
    float s = 0.f;
    for (int k = 0; k < K; k++) s += b[k] * w[(size_t)k * N + n];
    out[n] = s * scale;
}

// ---------------------------------------------------------------------------
// Plain LayerNorm (no gain/bias — folded into weights): fp32 -> fp16
// ---------------------------------------------------------------------------
__device__ __forceinline__ void ln_stats(const float* x, int C, int tid, int bdim,
                                         float& mean, float& inv) {
    float s = 0.f, s2 = 0.f;
    for (int i = tid; i < (C >> 2); i += bdim) {
        float4 v = *(const float4*)&x[4 * i];
        s  += v.x + v.y + v.z + v.w;
        s2 += v.x * v.x + v.y * v.y + v.z * v.z + v.w * v.w;
    }
    __shared__ float red[64];
    #pragma unroll
    for (int off = 16; off > 0; off >>= 1) {
        s  += __shfl_down_sync(0xffffffffu, s, off);
        s2 += __shfl_down_sync(0xffffffffu, s2, off);
    }
    int wid = tid >> 5, lid = tid & 31;
    if (lid == 0) { red[wid] = s; red[wid + 32] = s2; }
    __syncthreads();
    if (wid == 0) {
        int nw = bdim >> 5;
        s  = (lid < nw) ? red[lid] : 0.f;
        s2 = (lid < nw) ? red[lid + 32] : 0.f;
        #pragma unroll
        for (int off = 16; off > 0; off >>= 1) {
            s  += __shfl_down_sync(0xffffffffu, s, off);
            s2 += __shfl_down_sync(0xffffffffu, s2, off);
        }
        if (lid == 0) { red[0] = s; red[1] = s2; }
    }
    __syncthreads();
    mean = red[0] / C;
    float var = red[1] / C - mean * mean;
    inv = rsqrtf(var + 1e-5f);
}

__global__ void ln_plain(const float* __restrict__ in, __half* __restrict__ out, int C) {
    int row = blockIdx.x;
    const float* x = in + (size_t)row * C;
    uint32_t* o = (uint32_t*)(out + (size_t)row * C);
    float mean, inv;
    ln_stats(x, C, threadIdx.x, blockDim.x, mean, inv);
    for (int i = threadIdx.x; i < (C >> 1); i += blockDim.x) {
        float2 xv = *(const float2*)&x[2 * i];
        o[i] = packh((xv.x - mean) * inv, (xv.y - mean) * inv);
    }
}

// ---------------------------------------------------------------------------
// FP16 GEMM (R11-verified): 128x128 CTA, 128 threads, 4 warps 2x2, warp 64x64,
// 2-stage cp.async. outbf=1: fp16 out (+optional fp32 col-bias nbias);
// outbf=0: fp32 out + bias + residual.
// ---------------------------------------------------------------------------
#define GKS 72
#define GEMM_SMEM (2*2*128*GKS*2)

__global__ __launch_bounds__(128) void gemm_fp16(
    const __half* __restrict__ A, const __half* __restrict__ Bt,
    void* __restrict__ Cout, int M, int N, int K,
    const float* __restrict__ bias, const float* __restrict__ res, int outbf,
    const float* __restrict__ nbias)
{
    extern __shared__ __half smh[];
    __half* As = smh;
    __half* Bs = smh + 2 * 128 * GKS;
    int tid = threadIdx.x, lane = tid & 31, warp = tid >> 5;
    int t4 = lane & 3, g4 = lane >> 2;
    int wm = warp >> 1, wn = warp & 1;
    int m0 = blockIdx.y * 128, n0 = blockIdx.x * 128;

    int lrowA = ((lane >> 3) & 1) * 8 + (lane & 7);
    int lka   = (lane >> 4) * 8;
    int lrowB = (lane >> 4) * 8 + (lane & 7);
    int lkb   = ((lane >> 3) & 1) * 8;

    float acc[4][8][4];
    #pragma unroll
    for (int i = 0; i < 4; i++)
        #pragma unroll
        for (int j = 0; j < 8; j++)
            #pragma unroll
            for (int k = 0; k < 4; k++) acc[i][j][k] = 0.f;

    auto loadTile = [&](int kt, int s) {
        int k0 = kt * 64;
        __half* as = As + s * 128 * GKS;
        __half* bs = Bs + s * 128 * GKS;
        #pragma unroll
        for (int i = 0; i < 8; i++) {
            int c = tid + i * 128;
            int m = c >> 3, seg = c & 7;
            cp16(as + m * GKS + seg * 8, A + (size_t)(m0 + m) * K + k0 + seg * 8);
        }
        #pragma unroll
        for (int i = 0; i < 8; i++) {
            int c = tid + i * 128;
            int n = c >> 3, seg = c & 7;
            cp16(bs + n * GKS + seg * 8, Bt + (size_t)(n0 + n) * K + k0 + seg * 8);
        }
    };

    int nIter = K >> 6;
    loadTile(0, 0); cp_commit();
    int buf = 0;
    for (int kt = 0; kt < nIter; kt++) {
        if (kt + 1 < nIter) { loadTile(kt + 1, buf ^ 1); cp_commit(); cp_wait1(); }
        else                { cp_wait0(); }
        __syncthreads();
        const __half* as = As + buf * 128 * GKS;
        const __half* bs = Bs + buf * 128 * GKS;
        #pragma unroll
        for (int ks = 0; ks < 4; ks++) {
            uint32_t af[4][4];
            #pragma unroll
            for (int mf = 0; mf < 4; mf++)
                ldsm_x4(af[mf], as + (wm * 64 + mf * 16 + lrowA) * GKS + ks * 16 + lka);
            #pragma unroll
            for (int nf2 = 0; nf2 < 4; nf2++) {
                uint32_t bb[4];
                ldsm_x4(bb, bs + (wn * 64 + nf2 * 16 + lrowB) * GKS + ks * 16 + lkb);
                uint32_t b0[2] = { bb[0], bb[1] };
                uint32_t b1[2] = { bb[2], bb[3] };
                #pragma unroll
                for (int mf = 0; mf < 4; mf++) {
                    mma16(acc[mf][nf2 * 2],     af[mf], b0);
                    mma16(acc[mf][nf2 * 2 + 1], af[mf], b1);
                }
            }
        }
        __syncthreads();
        buf ^= 1;
    }

    if (outbf) {
        uint32_t* C2 = (uint32_t*)Cout;
        int N2 = N >> 1;
        #pragma unroll
        for (int mf = 0; mf < 4; mf++) {
            #pragma unroll
            for (int nf = 0; nf < 8; nf++) {
                int r  = m0 + wm * 64 + mf * 16 + g4;
                int cc = n0 + wn * 64 + nf * 8 + 2 * t4;
                float a0 = acc[mf][nf][0], a1 = acc[mf][nf][1];
                float a2 = acc[mf][nf][2], a3 = acc[mf][nf][3];
                if (nbias) {
                    float2 nb = *(const float2*)&nbias[cc];
                    a0 += nb.x; a1 += nb.y; a2 += nb.x; a3 += nb.y;
                }
                C2[(size_t)r * N2 + (cc >> 1)]       = packh(a0, a1);
                C2[(size_t)(r + 8) * N2 + (cc >> 1)] = packh(a2, a3);
            }
        }
    } else {
        float* C = (float*)Cout;
        #pragma unroll
        for (int mf = 0; mf < 4; mf++) {
            #pragma unroll
            for (int nf = 0; nf < 8; nf++) {
                int r  = m0 + wm * 64 + mf * 16 + g4;
                int cc = n0 + wn * 64 + nf * 8 + 2 * t4;
                float2 v0 = make_float2(acc[mf][nf][0], acc[mf][nf][1]);
                float2 v1 = make_float2(acc[mf][nf][2], acc[mf][nf][3]);
                float2 bv = *(const float2*)&bias[cc];
                v0.x += bv.x; v0.y += bv.y; v1.x += bv.x; v1.y += bv.y;
                float2 r0 = *(const float2*)&res[(size_t)r * N + cc];
                float2 r1 = *(const float2*)&res[(size_t)(r + 8) * N + cc];
                v0.x += r0.x; v0.y += r0.y; v1.x += r1.x; v1.y += r1.y;
                *(float2*)&C[(size_t)r * N + cc] = v0;
                *(float2*)&C[(size_t)(r + 8) * N + cc] = v1;
            }
        }
    }
}

// ---------------------------------------------------------------------------
// Merged QKV GEMM (self-attn): A = normalized x [M,1024], Bt = [wq'|wkv']
// [1536,1024]. Split epilogue: cols <512 -> Q buffer, >=512 -> KV buffer.
// Same verified mainloop as gemm_fp16.
// ---------------------------------------------------------------------------
__global__ __launch_bounds__(128) void gemm_qkv(
    const __half* __restrict__ A, const __half* __restrict__ Bt,
    __half* __restrict__ Qo, __half* __restrict__ KVo, int M, int K,
    const float* __restrict__ nbias)
{
    extern __shared__ __half smh[];
    __half* As = smh;
    __half* Bs = smh + 2 * 128 * GKS;
    int tid = threadIdx.x, lane = tid & 31, warp = tid >> 5;
    int t4 = lane & 3, g4 = lane >> 2;
    int wm = warp >> 1, wn = warp & 1;
    int m0 = blockIdx.y * 128, n0 = blockIdx.x * 128;

    int lrowA = ((lane >> 3) & 1) * 8 + (lane & 7);
    int lka   = (lane >> 4) * 8;
    int lrowB = (lane >> 4) * 8 + (lane & 7);
    int lkb   = ((lane >> 3) & 1) * 8;

    float acc[4][8][4];
    #pragma unroll
    for (int i = 0; i < 4; i++)
        #pragma unroll
        for (int j = 0; j < 8; j++)
            #pragma unroll
            for (int k = 0; k < 4; k++) acc[i][j][k] = 0.f;

    auto loadTile = [&](int kt, int s) {
        int k0 = kt * 64;
        __half* as = As + s * 128 * GKS;
        __half* bs = Bs + s * 128 * GKS;
        #pragma unroll
        for (int i = 0; i < 8; i++) {
            int c = tid + i * 128;
            int m = c >> 3, seg = c & 7;
            cp16(as + m * GKS + seg * 8, A + (size_t)(m0 + m) * K + k0 + seg * 8);
        }
        #pragma unroll
        for (int i = 0; i < 8; i++) {
            int c = tid + i * 128;
            int n = c >> 3, seg = c & 7;
            cp16(bs + n * GKS + seg * 8, Bt + (size_t)(n0 + n) * K + k0 + seg * 8);
        }
    };

    int nIter = K >> 6;
    loadTile(0, 0); cp_commit();
    int buf = 0;
    for (int kt = 0; kt < nIter; kt++) {
        if (kt + 1 < nIter) { loadTile(kt + 1, buf ^ 1); cp_commit(); cp_wait1(); }
        else                { cp_wait0(); }
        __syncthreads();
        const __half* as = As + buf * 128 * GKS;
        const __half* bs = Bs + buf * 128 * GKS;
        #pragma unroll
        for (int ks = 0; ks < 4; ks++) {
            uint32_t af[4][4];
            #pragma unroll
            for (int mf = 0; mf < 4; mf++)
                ldsm_x4(af[mf], as + (wm * 64 + mf * 16 + lrowA) * GKS + ks * 16 + lka);
            #pragma unroll
            for (int nf2 = 0; nf2 < 4; nf2++) {
                uint32_t bb[4];
                ldsm_x4(bb, bs + (wn * 64 + nf2 * 16 + lrowB) * GKS + ks * 16 + lkb);
                uint32_t b0[2] = { bb[0], bb[1] };
                uint32_t b1[2] = { bb[2], bb[3] };
                #pragma unroll
                for (int mf = 0; mf < 4; mf++) {
                    mma16(acc[mf][nf2 * 2],     af[mf], b0);
                    mma16(acc[mf][nf2 * 2 + 1], af[mf], b1);
                }
            }
        }
        __syncthreads();
        buf ^= 1;
    }

    // split epilogue (per-CTA uniform branch: tiles never straddle col 512)
    uint32_t* C2 = (n0 < 512) ? (uint32_t*)Qo : (uint32_t*)KVo;
    int N2      = (n0 < 512) ? (MIDW >> 1)    : MIDW;        // u32 row stride
    int coff    = (n0 < 512) ? 0              : 512;
    #pragma unroll
    for (int mf = 0; mf < 4; mf++) {
        #pragma unroll
        for (int nf = 0; nf < 8; nf++) {
            int r  = m0 + wm * 64 + mf * 16 + g4;
            int cc = n0 + wn * 64 + nf * 8 + 2 * t4;
            float2 nb = *(const float2*)&nbias[cc];
            float a0 = acc[mf][nf][0] + nb.x, a1 = acc[mf][nf][1] + nb.y;
            float a2 = acc[mf][nf][2] + nb.x, a3 = acc[mf][nf][3] + nb.y;
            int cl = cc - coff;
            C2[(size_t)r * N2 + (cl >> 1)]       = packh(a0, a1);
            C2[(size_t)(r + 8) * N2 + (cl >> 1)] = packh(a2, a3);
        }
    }
}

// ---------------------------------------------------------------------------
// FP16 flash (R11-verified): 128 threads, 4 warps x 32 rows, max-free softmax
// ---------------------------------------------------------------------------
#define KST 72
#define FL_SMEM (2*(64*KST + 64*KST)*2)

__global__ __launch_bounds__(128) void flash_fp16(
    const __half* __restrict__ Q, const __half* __restrict__ KV,
    __half* __restrict__ O, int m_len)
{
    extern __shared__ __half fsm[];
    __half* Ks = fsm;
    __half* Vs = fsm + 2 * 64 * KST;
    int tid = threadIdx.x, lane = tid & 31, warp = tid >> 5;
    int t4 = lane & 3, g4 = lane >> 2;
    int bh = blockIdx.y, b = bh >> 3, h = bh & 7;
    int hoff = h * DD;
    int qb = b * NQ + blockIdx.x * 128;
    int kvb = b * m_len;

    int lrowK = ((lane >> 4) & 1) * 8 + (lane & 7);
    int lkb   = ((lane >> 3) & 1) * 8;

    uint32_t qf[4][2][4];
    {
        const uint32_t* qu = (const uint32_t*)Q;
        #pragma unroll
        for (int mf = 0; mf < 2; mf++) {
            int r = qb + warp * 32 + mf * 16 + g4;
            size_t base0 = (size_t)r * (MIDW / 2) + (hoff >> 1);
            size_t base1 = base0 + 8 * (MIDW / 2);
            #pragma unroll
            for (int ks = 0; ks < 4; ks++) {
                qf[ks][mf][0] = qu[base0 + ks * 8 + t4];
                qf[ks][mf][1] = qu[base1 + ks * 8 + t4];
                qf[ks][mf][2] = qu[base0 + ks * 8 + t4 + 4];
                qf[ks][mf][3] = qu[base1 + ks * 8 + t4 + 4];
            }
        }
    }

    float o[2][8][4];
    #pragma unroll
    for (int mf = 0; mf < 2; mf++)
        #pragma unroll
        for (int i = 0; i < 8; i++)
            #pragma unroll
            for (int j = 0; j < 4; j++) o[mf][i][j] = 0.f;
    float lr[2][2] = {{0.f, 0.f}, {0.f, 0.f}};

    auto loadKV = [&](int mt, int bufi) {
        int kb = kvb + mt * 64;
        __half* ks = Ks + bufi * 64 * KST;
        __half* vs = Vs + bufi * 64 * KST;
        #pragma unroll
        for (int i = 0; i < 8; i++) {
            int c = tid + i * 128;
            int key = c >> 4, seg = c & 15;
            const __half* row = KV + (size_t)(kb + key) * (2 * MIDW);
            if (seg < 8) cp16(ks + key * KST + seg * 8, row + hoff + seg * 8);
            else         cp16(vs + key * KST + (seg - 8) * 8, row + MIDW + hoff + (seg - 8) * 8);
        }
    };

    int nt = m_len >> 6;
    loadKV(0, 0); cp_commit();
    int buf = 0;
    for (int mt = 0; mt < nt; mt++) {
        if (mt + 1 < nt) { loadKV(mt + 1, buf ^ 1); cp_commit(); cp_wait1(); }
        else             { cp_wait0(); }
        __syncthreads();
        const __half* ksb = Ks + buf * 64 * KST;
        const __half* vsb = Vs + buf * 64 * KST;

        float sa[2][8][4];
        #pragma unroll
        for (int mf = 0; mf < 2; mf++)
            #pragma unroll
            for (int i = 0; i < 8; i++)
                #pragma unroll
                for (int j = 0; j < 4; j++) sa[mf][i][j] = 0.f;
        #pragma unroll
        for (int ks = 0; ks < 4; ks++) {
            #pragma unroll
            for (int nf2 = 0; nf2 < 4; nf2++) {
                uint32_t bb[4];
                ldsm_x4(bb, ksb + (nf2 * 16 + lrowK) * KST + ks * 16 + lkb);
                uint32_t b0[2] = { bb[0], bb[1] };
                uint32_t b1[2] = { bb[2], bb[3] };
                #pragma unroll
                for (int mf = 0; mf < 2; mf++) {
                    mma16(sa[mf][nf2 * 2],     qf[ks][mf], b0);
                    mma16(sa[mf][nf2 * 2 + 1], qf[ks][mf], b1);
                }
            }
        }

        uint32_t pf[4][2][4];
        #pragma unroll
        for (int mf = 0; mf < 2; mf++) {
            float s0 = 0.f, s1 = 0.f;
            #pragma unroll
            for (int kb2 = 0; kb2 < 4; kb2++) {
                float p00 = ex2f(sa[mf][2*kb2][0]),   p01 = ex2f(sa[mf][2*kb2][1]);
                float p02 = ex2f(sa[mf][2*kb2][2]),   p03 = ex2f(sa[mf][2*kb2][3]);
                float p10 = ex2f(sa[mf][2*kb2+1][0]), p11 = ex2f(sa[mf][2*kb2+1][1]);
                float p12 = ex2f(sa[mf][2*kb2+1][2]), p13 = ex2f(sa[mf][2*kb2+1][3]);
                s0 += p00 + p01 + p10 + p11;
                s1 += p02 + p03 + p12 + p13;
                pf[kb2][mf][0] = packh(p00, p01);
                pf[kb2][mf][1] = packh(p02, p03);
                pf[kb2][mf][2] = packh(p10, p11);
                pf[kb2][mf][3] = packh(p12, p13);
            }
            lr[mf][0] += s0; lr[mf][1] += s1;
        }

        #pragma unroll
        for (int kb2 = 0; kb2 < 4; kb2++) {
            #pragma unroll
            for (int nf2 = 0; nf2 < 4; nf2++) {
                uint32_t vreg[4];
                int vrow = kb2 * 16 + ((lane >> 3) & 1) * 8 + (lane & 7);
                int vcol = nf2 * 16 + (lane >> 4) * 8;
                ldsm_x4_trans(vreg, vsb + vrow * KST + vcol);
                uint32_t b0[2] = { vreg[0], vreg[1] };
                uint32_t b1[2] = { vreg[2], vreg[3] };
                #pragma unroll
                for (int mf = 0; mf < 2; mf++) {
                    mma16(o[mf][nf2 * 2],     pf[kb2][mf], b0);
                    mma16(o[mf][nf2 * 2 + 1], pf[kb2][mf], b1);
                }
            }
        }
        __syncthreads();
        buf ^= 1;
    }

    uint32_t* Ou = (uint32_t*)O;
    #pragma unroll
    for (int mf = 0; mf < 2; mf++) {
        float l0 = lr[mf][0], l1 = lr[mf][1];
        l0 += __shfl_xor_sync(0xffffffffu, l0, 1);
        l0 += __shfl_xor_sync(0xffffffffu, l0, 2);
        l1 += __shfl_xor_sync(0xffffffffu, l1, 1);
        l1 += __shfl_xor_sync(0xffffffffu, l1, 2);
        float inv0 = 1.f / l0, inv1 = 1.f / l1;
        int r = qb + warp * 32 + mf * 16 + g4;
        size_t ob0 = (size_t)r * (MIDW / 2) + (hoff >> 1);
        size_t ob1 = ob0 + 8 * (MIDW / 2);
        #pragma unroll
        for (int nf = 0; nf < 8; nf++) {
            int ci = nf * 4 + t4;
            Ou[ob0 + ci] = packh(o[mf][nf][0] * inv0, o[mf][nf][1] * inv0);
            Ou[ob1 + ci] = packh(o[mf][nf][2] * inv1, o[mf][nf][3] * inv1);
        }
    }
}

// ---------------------------------------------------------------------------
// Launch: fused-affine graph with multi-stream fork/join
// ---------------------------------------------------------------------------
extern "C" void kernel_launch(void* const* d_in, const int* in_sizes, int n_in,
                              void* d_out, int out_size) {
    const float* x      = (const float*)d_in[0];
    const float* ctx    = (const float*)d_in[1];
    const float* sa_ng  = (const float*)d_in[2];
    const float* sa_nb  = (const float*)d_in[3];
    const float* sa_ncg = (const float*)d_in[4];
    const float* sa_ncb = (const float*)d_in[5];
    const float* sa_wq  = (const float*)d_in[6];
    const float* sa_wkv = (const float*)d_in[7];
    const float* sa_wo  = (const float*)d_in[8];
    const float* sa_bo  = (const float*)d_in[9];
    const float* ca_ng  = (const float*)d_in[10];
    const float* ca_nb  = (const float*)d_in[11];
    const float* ca_ncg = (const float*)d_in[12];
    const float* ca_ncb = (const float*)d_in[13];
    const float* ca_wq  = (const float*)d_in[14];
    const float* ca_wkv = (const float*)d_in[15];
    const float* ca_wo  = (const float*)d_in[16];
    const float* ca_bo  = (const float*)d_in[17];
    float* out = (float*)d_out;

    __half *xn, *cx, *q, *kv, *ao, *wt;
    float* nb;
    cudaGetSymbolAddress((void**)&xn, g_xn);
    cudaGetSymbolAddress((void**)&cx, g_cx);
    cudaGetSymbolAddress((void**)&q,  g_q);
    cudaGetSymbolAddress((void**)&kv, g_kv);
    cudaGetSymbolAddress((void**)&ao, g_ao);
    cudaGetSymbolAddress((void**)&wt, g_wt);
    cudaGetSymbolAddress((void**)&nb, g_nb);

    static bool inited = false;
    static cudaStream_t s1, s2;
    static cudaEvent_t eFork, eW1, eW2, eC, eLN, eB1, eB2, eF1, eKV2;
    if (!inited) {
        cudaStreamCreateWithFlags(&s1, cudaStreamNonBlocking);
        cudaStreamCreateWithFlags(&s2, cudaStreamNonBlocking);
        cudaEventCreateWithFlags(&eFork, cudaEventDisableTiming);
        cudaEventCreateWithFlags(&eW1, cudaEventDisableTiming);
        cudaEventCreateWithFlags(&eW2, cudaEventDisableTiming);
        cudaEventCreateWithFlags(&eC,  cudaEventDisableTiming);
        cudaEventCreateWithFlags(&eLN, cudaEventDisableTiming);
        cudaEventCreateWithFlags(&eB1, cudaEventDisableTiming);
        cudaEventCreateWithFlags(&eB2, cudaEventDisableTiming);
        cudaEventCreateWithFlags(&eF1, cudaEventDisableTiming);
        cudaEventCreateWithFlags(&eKV2, cudaEventDisableTiming);
        cudaFuncSetAttribute(gemm_fp16, cudaFuncAttributeMaxDynamicSharedMemorySize, GEMM_SMEM);
        cudaFuncSetAttribute(gemm_qkv,  cudaFuncAttributeMaxDynamicSharedMemorySize, GEMM_SMEM);
        cudaFuncSetAttribute(flash_fp16, cudaFuncAttributeMaxDynamicSharedMemorySize, FL_SMEM);
        inited = true;
    }

    dim3 tb(32, 8);

    cudaEventRecord(eFork, 0);
    cudaStreamWaitEvent(s1, eFork, 0);
    cudaStreamWaitEvent(s2, eFork, 0);

    // Phase A: plain LN(x) on s0 | sa weight prep on s1 | sa bias vectors on s2
    ln_plain<<<ROWS, 256>>>(x, xn, FF);
    cudaEventRecord(eLN, 0);

    wtrans_kernel<<<dim3(MIDW/32, FF/32),   tb, 0, s1>>>(sa_wq,  wt + OFF_SA_WQ,  FF, MIDW, sa_ng, QK_SCALE);
    wtrans_kernel<<<dim3(2*MIDW/32, FF/32), tb, 0, s1>>>(sa_wkv, wt + OFF_SA_WKV, FF, 2*MIDW, sa_ncg, 1.f);
    cudaEventRecord(eW1, s1);

    bvec_kernel<<<MIDW/256, 256, 0, s2>>>(sa_nb,  sa_wq,  nb + NB_SA,       FF, MIDW,   QK_SCALE);
    bvec_kernel<<<2*MIDW/256, 256, 0, s2>>>(sa_ncb, sa_wkv, nb + NB_SA + 512, FF, 2*MIDW, 1.f);
    cudaEventRecord(eB1, s2);

    // Phase B: merged QKV gemm (768 CTAs) on s0
    cudaStreamWaitEvent(0, eW1, 0);
    cudaStreamWaitEvent(0, eB1, 0);
    gemm_qkv<<<dim3(1536/128, ROWS/128), 128, GEMM_SMEM>>>(
        xn, wt + OFF_SA_WQ, q, kv, ROWS, FF, nb + NB_SA);

    // Phase C: flash-sa on s0
    flash_fp16<<<dim3(NQ/128, BB*HH), 128, FL_SMEM>>>(q, kv, ao, NQ);
    cudaEventRecord(eF1, 0);

    // overlap flash: remaining weight prep on s1, ca biases + ctx LN on s2
    wtrans_kernel<<<dim3(FF/32, MIDW/32),   tb, 0, s1>>>(sa_wo,  wt + OFF_SA_WO,  MIDW, FF, nullptr, 1.f);
    wtrans_kernel<<<dim3(MIDW/32, FF/32),   tb, 0, s1>>>(ca_wq,  wt + OFF_CA_WQ,  FF, MIDW, ca_ng, QK_SCALE);
    wtrans_kernel<<<dim3(2*MIDW/32, CFF/32),tb, 0, s1>>>(ca_wkv, wt + OFF_CA_WKV, CFF, 2*MIDW, ca_ncg, 1.f);
    wtrans_kernel<<<dim3(FF/32, MIDW/32),   tb, 0, s1>>>(ca_wo,  wt + OFF_CA_WO,  MIDW, FF, nullptr, 1.f);
    cudaEventRecord(eW2, s1);

    bvec_kernel<<<MIDW/256, 256, 0, s2>>>(ca_nb,  ca_wq,  nb + NB_CA_Q,  FF,  MIDW,   QK_SCALE);
    bvec_kernel<<<2*MIDW/256, 256, 0, s2>>>(ca_ncb, ca_wkv, nb + NB_CA_KV, CFF, 2*MIDW, 1.f);
    ln_plain<<<CROWS, 256, 0, s2>>>(ctx, cx, CFF);
    cudaEventRecord(eC, s2);

    // Phase D: WO-gemm-sa on s0 (fp32 out + bias + residual x)
    cudaStreamWaitEvent(0, eW2, 0);
    gemm_fp16<<<dim3(FF/128, ROWS/128), 128, GEMM_SMEM>>>(
        ao, wt + OFF_SA_WO, out, ROWS, FF, MIDW, sa_bo, x, 0, nullptr);

    // Phase E: LN(out) + Q-gemm-ca on s0
    ln_plain<<<ROWS, 256>>>(out, xn, FF);
    cudaStreamWaitEvent(0, eC, 0);   // ca bias vectors ready
    gemm_fp16<<<dim3(MIDW/128, ROWS/128), 128, GEMM_SMEM>>>(
        xn, wt + OFF_CA_WQ, q, ROWS, MIDW, FF, nullptr, nullptr, 1, nb + NB_CA_Q);

    // Phase F: KV-gemm-ca on s1 (after flash-sa frees kv; ctx LN + biases done)
    cudaStreamWaitEvent(s1, eF1, 0);
    cudaStreamWaitEvent(s1, eC, 0);
    gemm_fp16<<<dim3(2*MIDW/128, CROWS/128), 128, GEMM_SMEM, s1>>>(
        cx, wt + OFF_CA_WKV, kv, CROWS, 2*MIDW, CFF, nullptr, nullptr, 1, nb + NB_CA_KV);
    cudaEventRecord(eKV2, s1);

    // Phase G: flash-ca + WO-gemm-ca on s0
    cudaStreamWaitEvent(0, eKV2, 0);
    flash_fp16<<<dim3(NQ/128, BB*HH), 128, FL_SMEM>>>(q, kv, ao, 512);
    gemm_fp16<<<dim3(FF/128, ROWS/128), 128, GEMM_SMEM>>>(
        ao, wt + OFF_CA_WO, out, ROWS, FF, MIDW, ca_bo, out, 0, nullptr);
}

// round 14
// speedup vs baseline: 1.2881x; 1.2881x over previous
#include <cuda_runtime.h>
#include <cuda_fp16.h>
#include <math.h>
#include <stdint.h>

#define BB 4
#define NQ 2048
#define FF 1024
#define CFF 768
#define HH 8
#define DD 64
#define MIDW 512
#define ROWS (BB*NQ)        // 8192
#define CROWS (BB*512)      // 2048
#define QK_SCALE (0.125f * 1.4426950408889634f)

// Scratch (device globals, fp16 activations)
__device__ __half g_xn[ROWS*FF];
__device__ __half g_cx[CROWS*CFF];
__device__ __half g_q [ROWS*MIDW];
__device__ __half g_kv[ROWS*2*MIDW];
__device__ __half g_ao[ROWS*MIDW];
__device__ __half g_wt[4*1024*1024];
__device__ float  g_nb[4096];          // folded LN-bias column vectors

#define OFF_SA_WQ  0                   // rows 0-511   of merged sa B (N=1536)
#define OFF_SA_WKV 524288              // rows 512-1535
#define OFF_SA_WO  1572864
#define OFF_CA_WQ  2097152
#define OFF_CA_WKV 2621440
#define OFF_CA_WO  3407872
#define NB_SA   0                      // 1536 entries (q:0-511, kv:512-1535)
#define NB_CA_Q 2048                   // 512
#define NB_CA_KV 2560                  // 1024

// ---------------------------------------------------------------------------
// helpers
// ---------------------------------------------------------------------------
__device__ __forceinline__ void cp16(void* dst, const void* src) {
    uint32_t d = (uint32_t)__cvta_generic_to_shared(dst);
    asm volatile("cp.async.cg.shared.global [%0], [%1], 16;\n" :: "r"(d), "l"(src));
}
__device__ __forceinline__ void cp_commit() { asm volatile("cp.async.commit_group;\n" ::: "memory"); }
__device__ __forceinline__ void cp_wait0()  { asm volatile("cp.async.wait_group 0;\n" ::: "memory"); }
__device__ __forceinline__ void cp_wait1()  { asm volatile("cp.async.wait_group 1;\n" ::: "memory"); }

__device__ __forceinline__ void mma16(float (&d)[4], const uint32_t (&a)[4],
                                      const uint32_t (&b)[2]) {
    asm volatile(
        "mma.sync.aligned.m16n8k16.row.col.f32.f16.f16.f32 "
        "{%0,%1,%2,%3},{%4,%5,%6,%7},{%8,%9},{%0,%1,%2,%3};\n"
        : "+f"(d[0]), "+f"(d[1]), "+f"(d[2]), "+f"(d[3])
        : "r"(a[0]), "r"(a[1]), "r"(a[2]), "r"(a[3]), "r"(b[0]), "r"(b[1]));
}
__device__ __forceinline__ uint32_t packh(float lo, float hi) {
    uint32_t r;
    asm("cvt.rn.f16x2.f32 %0, %1, %2;\n" : "=r"(r) : "f"(hi), "f"(lo));
    return r;
}
__device__ __forceinline__ float ex2f(float x) {
    float y; asm("ex2.approx.f32 %0, %1;\n" : "=f"(y) : "f"(x)); return y;
}
__device__ __forceinline__ void ldsm_x4(uint32_t (&r)[4], const void* p) {
    uint32_t a = (uint32_t)__cvta_generic_to_shared(p);
    asm volatile("ldmatrix.sync.aligned.m8n8.x4.shared.b16 {%0,%1,%2,%3}, [%4];\n"
                 : "=r"(r[0]), "=r"(r[1]), "=r"(r[2]), "=r"(r[3]) : "r"(a));
}
__device__ __forceinline__ void ldsm_x4_trans(uint32_t (&r)[4], const void* p) {
    uint32_t a = (uint32_t)__cvta_generic_to_shared(p);
    asm volatile("ldmatrix.sync.aligned.m8n8.x4.trans.shared.b16 {%0,%1,%2,%3}, [%4];\n"
                 : "=r"(r[0]), "=r"(r[1]), "=r"(r[2]), "=r"(r[3]) : "r"(a));
}

// ---------------------------------------------------------------------------
// Weight transpose + gain-fold + scale: fp32 [K][N] -> fp16 [N][K]
// ---------------------------------------------------------------------------
__global__ void wtrans_kernel(const float* __restrict__ in, __half* __restrict__ out,
                              int K, int N, const float* __restrict__ gain, float scale) {
    __shared__ float t[32][33];
    int n0 = blockIdx.x * 32, k0 = blockIdx.y * 32;
    int tx = threadIdx.x, ty = threadIdx.y;
    #pragma unroll
    for (int i = 0; i < 4; i++)
        t[ty + i * 8][tx] = in[(size_t)(k0 + ty + i * 8) * N + n0 + tx];
    __syncthreads();
    float gk = (gain ? gain[k0 + tx] : 1.f) * scale;
    #pragma unroll
    for (int i = 0; i < 4; i++)
        out[(size_t)(n0 + ty + i * 8) * K + k0 + tx] = __float2half(t[tx][ty + i * 8] * gk);
}

// bias vector: out[n] = scale * sum_k b[k] * w[k][n]
// block = 512 threads = 64 columns x 8 K-slices; grid = N/64
__global__ __launch_bounds__(512) void bvec_kernel(
    const float* __restrict__ b, const float* __restrict__ w,
    float* __restrict__ out, int K, int N, float scale)
{
    __shared__ float red[512];
    int col = blockIdx.x * 64 + (threadIdx.x & 63);
    int slice = threadIdx.x >> 6;          // 0..7
    int kn = K >> 3;
    int k0 = slice * kn;
    float s = 0.f;
    #pragma unroll 4
    for (int k = k0; k < k0 + kn; k++)
        s += b[k] * w[(size_t)k * N + col];
    red[threadIdx.x] = s;
    __syncthreads();
    if (threadIdx.x < 64) {
        float t = 0.f;
        #pragma unroll
        for (int i = 0; i < 8; i++) t += red[i * 64 + threadIdx.x];
        out[col] = t * scale;
    }
}

// ---------------------------------------------------------------------------
// Plain LayerNorm (gain/bias folded into weights): fp32 -> fp16
// ---------------------------------------------------------------------------
__device__ __forceinline__ void ln_stats(const float* x, int C, int tid, int bdim,
                                         float& mean, float& inv) {
    float s = 0.f, s2 = 0.f;
    for (int i = tid; i < (C >> 2); i += bdim) {
        float4 v = *(const float4*)&x[4 * i];
        s  += v.x + v.y + v.z + v.w;
        s2 += v.x * v.x + v.y * v.y + v.z * v.z + v.w * v.w;
    }
    __shared__ float red[64];
    #pragma unroll
    for (int off = 16; off > 0; off >>= 1) {
        s  += __shfl_down_sync(0xffffffffu, s, off);
        s2 += __shfl_down_sync(0xffffffffu, s2, off);
    }
    int wid = tid >> 5, lid = tid & 31;
    if (lid == 0) { red[wid] = s; red[wid + 32] = s2; }
    __syncthreads();
    if (wid == 0) {
        int nw = bdim >> 5;
        s  = (lid < nw) ? red[lid] : 0.f;
        s2 = (lid < nw) ? red[lid + 32] : 0.f;
        #pragma unroll
        for (int off = 16; off > 0; off >>= 1) {
            s  += __shfl_down_sync(0xffffffffu, s, off);
            s2 += __shfl_down_sync(0xffffffffu, s2, off);
        }
        if (lid == 0) { red[0] = s; red[1] = s2; }
    }
    __syncthreads();
    mean = red[0] / C;
    float var = red[1] / C - mean * mean;
    inv = rsqrtf(var + 1e-5f);
}

__global__ void ln_plain(const float* __restrict__ in, __half* __restrict__ out, int C) {
    int row = blockIdx.x;
    const float* x = in + (size_t)row * C;
    uint32_t* o = (uint32_t*)(out + (size_t)row * C);
    float mean, inv;
    ln_stats(x, C, threadIdx.x, blockDim.x, mean, inv);
    for (int i = threadIdx.x; i < (C >> 1); i += blockDim.x) {
        float2 xv = *(const float2*)&x[2 * i];
        o[i] = packh((xv.x - mean) * inv, (xv.y - mean) * inv);
    }
}

// ---------------------------------------------------------------------------
// FP16 GEMM (R11-verified): 128x128 CTA, 128 threads, 4 warps 2x2, warp 64x64.
// ---------------------------------------------------------------------------
#define GKS 72
#define GEMM_SMEM (2*2*128*GKS*2)

__global__ __launch_bounds__(128) void gemm_fp16(
    const __half* __restrict__ A, const __half* __restrict__ Bt,
    void* __restrict__ Cout, int M, int N, int K,
    const float* __restrict__ bias, const float* __restrict__ res, int outbf,
    const float* __restrict__ nbias)
{
    extern __shared__ __half smh[];
    __half* As = smh;
    __half* Bs = smh + 2 * 128 * GKS;
    int tid = threadIdx.x, lane = tid & 31, warp = tid >> 5;
    int t4 = lane & 3, g4 = lane >> 2;
    int wm = warp >> 1, wn = warp & 1;
    int m0 = blockIdx.y * 128, n0 = blockIdx.x * 128;

    int lrowA = ((lane >> 3) & 1) * 8 + (lane & 7);
    int lka   = (lane >> 4) * 8;
    int lrowB = (lane >> 4) * 8 + (lane & 7);
    int lkb   = ((lane >> 3) & 1) * 8;

    float acc[4][8][4];
    #pragma unroll
    for (int i = 0; i < 4; i++)
        #pragma unroll
        for (int j = 0; j < 8; j++)
            #pragma unroll
            for (int k = 0; k < 4; k++) acc[i][j][k] = 0.f;

    auto loadTile = [&](int kt, int s) {
        int k0 = kt * 64;
        __half* as = As + s * 128 * GKS;
        __half* bs = Bs + s * 128 * GKS;
        #pragma unroll
        for (int i = 0; i < 8; i++) {
            int c = tid + i * 128;
            int m = c >> 3, seg = c & 7;
            cp16(as + m * GKS + seg * 8, A + (size_t)(m0 + m) * K + k0 + seg * 8);
        }
        #pragma unroll
        for (int i = 0; i < 8; i++) {
            int c = tid + i * 128;
            int n = c >> 3, seg = c & 7;
            cp16(bs + n * GKS + seg * 8, Bt + (size_t)(n0 + n) * K + k0 + seg * 8);
        }
    };

    int nIter = K >> 6;
    loadTile(0, 0); cp_commit();
    int buf = 0;
    for (int kt = 0; kt < nIter; kt++) {
        if (kt + 1 < nIter) { loadTile(kt + 1, buf ^ 1); cp_commit(); cp_wait1(); }
        else                { cp_wait0(); }
        __syncthreads();
        const __half* as = As + buf * 128 * GKS;
        const __half* bs = Bs + buf * 128 * GKS;
        #pragma unroll
        for (int ks = 0; ks < 4; ks++) {
            uint32_t af[4][4];
            #pragma unroll
            for (int mf = 0; mf < 4; mf++)
                ldsm_x4(af[mf], as + (wm * 64 + mf * 16 + lrowA) * GKS + ks * 16 + lka);
            #pragma unroll
            for (int nf2 = 0; nf2 < 4; nf2++) {
                uint32_t bb[4];
                ldsm_x4(bb, bs + (wn * 64 + nf2 * 16 + lrowB) * GKS + ks * 16 + lkb);
                uint32_t b0[2] = { bb[0], bb[1] };
                uint32_t b1[2] = { bb[2], bb[3] };
                #pragma unroll
                for (int mf = 0; mf < 4; mf++) {
                    mma16(acc[mf][nf2 * 2],     af[mf], b0);
                    mma16(acc[mf][nf2 * 2 + 1], af[mf], b1);
                }
            }
        }
        __syncthreads();
        buf ^= 1;
    }

    if (outbf) {
        uint32_t* C2 = (uint32_t*)Cout;
        int N2 = N >> 1;
        #pragma unroll
        for (int mf = 0; mf < 4; mf++) {
            #pragma unroll
            for (int nf = 0; nf < 8; nf++) {
                int r  = m0 + wm * 64 + mf * 16 + g4;
                int cc = n0 + wn * 64 + nf * 8 + 2 * t4;
                float a0 = acc[mf][nf][0], a1 = acc[mf][nf][1];
                float a2 = acc[mf][nf][2], a3 = acc[mf][nf][3];
                if (nbias) {
                    float2 nb = *(const float2*)&nbias[cc];
                    a0 += nb.x; a1 += nb.y; a2 += nb.x; a3 += nb.y;
                }
                C2[(size_t)r * N2 + (cc >> 1)]       = packh(a0, a1);
                C2[(size_t)(r + 8) * N2 + (cc >> 1)] = packh(a2, a3);
            }
        }
    } else {
        float* C = (float*)Cout;
        #pragma unroll
        for (int mf = 0; mf < 4; mf++) {
            #pragma unroll
            for (int nf = 0; nf < 8; nf++) {
                int r  = m0 + wm * 64 + mf * 16 + g4;
                int cc = n0 + wn * 64 + nf * 8 + 2 * t4;
                float2 v0 = make_float2(acc[mf][nf][0], acc[mf][nf][1]);
                float2 v1 = make_float2(acc[mf][nf][2], acc[mf][nf][3]);
                float2 bv = *(const float2*)&bias[cc];
                v0.x += bv.x; v0.y += bv.y; v1.x += bv.x; v1.y += bv.y;
                float2 r0 = *(const float2*)&res[(size_t)r * N + cc];
                float2 r1 = *(const float2*)&res[(size_t)(r + 8) * N + cc];
                v0.x += r0.x; v0.y += r0.y; v1.x += r1.x; v1.y += r1.y;
                *(float2*)&C[(size_t)r * N + cc] = v0;
                *(float2*)&C[(size_t)(r + 8) * N + cc] = v1;
            }
        }
    }
}

// ---------------------------------------------------------------------------
// Merged QKV GEMM (self-attn): split epilogue Q/KV. Verified mainloop.
// ---------------------------------------------------------------------------
__global__ __launch_bounds__(128) void gemm_qkv(
    const __half* __restrict__ A, const __half* __restrict__ Bt,
    __half* __restrict__ Qo, __half* __restrict__ KVo, int M, int K,
    const float* __restrict__ nbias)
{
    extern __shared__ __half smh[];
    __half* As = smh;
    __half* Bs = smh + 2 * 128 * GKS;
    int tid = threadIdx.x, lane = tid & 31, warp = tid >> 5;
    int t4 = lane & 3, g4 = lane >> 2;
    int wm = warp >> 1, wn = warp & 1;
    int m0 = blockIdx.y * 128, n0 = blockIdx.x * 128;

    int lrowA = ((lane >> 3) & 1) * 8 + (lane & 7);
    int lka   = (lane >> 4) * 8;
    int lrowB = (lane >> 4) * 8 + (lane & 7);
    int lkb   = ((lane >> 3) & 1) * 8;

    float acc[4][8][4];
    #pragma unroll
    for (int i = 0; i < 4; i++)
        #pragma unroll
        for (int j = 0; j < 8; j++)
            #pragma unroll
            for (int k = 0; k < 4; k++) acc[i][j][k] = 0.f;

    auto loadTile = [&](int kt, int s) {
        int k0 = kt * 64;
        __half* as = As + s * 128 * GKS;
        __half* bs = Bs + s * 128 * GKS;
        #pragma unroll
        for (int i = 0; i < 8; i++) {
            int c = tid + i * 128;
            int m = c >> 3, seg = c & 7;
            cp16(as + m * GKS + seg * 8, A + (size_t)(m0 + m) * K + k0 + seg * 8);
        }
        #pragma unroll
        for (int i = 0; i < 8; i++) {
            int c = tid + i * 128;
            int n = c >> 3, seg = c & 7;
            cp16(bs + n * GKS + seg * 8, Bt + (size_t)(n0 + n) * K + k0 + seg * 8);
        }
    };

    int nIter = K >> 6;
    loadTile(0, 0); cp_commit();
    int buf = 0;
    for (int kt = 0; kt < nIter; kt++) {
        if (kt + 1 < nIter) { loadTile(kt + 1, buf ^ 1); cp_commit(); cp_wait1(); }
        else                { cp_wait0(); }
        __syncthreads();
        const __half* as = As + buf * 128 * GKS;
        const __half* bs = Bs + buf * 128 * GKS;
        #pragma unroll
        for (int ks = 0; ks < 4; ks++) {
            uint32_t af[4][4];
            #pragma unroll
            for (int mf = 0; mf < 4; mf++)
                ldsm_x4(af[mf], as + (wm * 64 + mf * 16 + lrowA) * GKS + ks * 16 + lka);
            #pragma unroll
            for (int nf2 = 0; nf2 < 4; nf2++) {
                uint32_t bb[4];
                ldsm_x4(bb, bs + (wn * 64 + nf2 * 16 + lrowB) * GKS + ks * 16 + lkb);
                uint32_t b0[2] = { bb[0], bb[1] };
                uint32_t b1[2] = { bb[2], bb[3] };
                #pragma unroll
                for (int mf = 0; mf < 4; mf++) {
                    mma16(acc[mf][nf2 * 2],     af[mf], b0);
                    mma16(acc[mf][nf2 * 2 + 1], af[mf], b1);
                }
            }
        }
        __syncthreads();
        buf ^= 1;
    }

    uint32_t* C2 = (n0 < 512) ? (uint32_t*)Qo : (uint32_t*)KVo;
    int N2      = (n0 < 512) ? (MIDW >> 1)    : MIDW;
    int coff    = (n0 < 512) ? 0              : 512;
    #pragma unroll
    for (int mf = 0; mf < 4; mf++) {
        #pragma unroll
        for (int nf = 0; nf < 8; nf++) {
            int r  = m0 + wm * 64 + mf * 16 + g4;
            int cc = n0 + wn * 64 + nf * 8 + 2 * t4;
            float2 nb = *(const float2*)&nbias[cc];
            float a0 = acc[mf][nf][0] + nb.x, a1 = acc[mf][nf][1] + nb.y;
            float a2 = acc[mf][nf][2] + nb.x, a3 = acc[mf][nf][3] + nb.y;
            int cl = cc - coff;
            C2[(size_t)r * N2 + (cl >> 1)]       = packh(a0, a1);
            C2[(size_t)(r + 8) * N2 + (cl >> 1)] = packh(a2, a3);
        }
    }
}

// ---------------------------------------------------------------------------
// FP16 flash (R11-verified): 128 threads, 4 warps x 32 rows, max-free softmax
// ---------------------------------------------------------------------------
#define KST 72
#define FL_SMEM (2*(64*KST + 64*KST)*2)

__global__ __launch_bounds__(128) void flash_fp16(
    const __half* __restrict__ Q, const __half* __restrict__ KV,
    __half* __restrict__ O, int m_len)
{
    extern __shared__ __half fsm[];
    __half* Ks = fsm;
    __half* Vs = fsm + 2 * 64 * KST;
    int tid = threadIdx.x, lane = tid & 31, warp = tid >> 5;
    int t4 = lane & 3, g4 = lane >> 2;
    int bh = blockIdx.y, b = bh >> 3, h = bh & 7;
    int hoff = h * DD;
    int qb = b * NQ + blockIdx.x * 128;
    int kvb = b * m_len;

    int lrowK = ((lane >> 4) & 1) * 8 + (lane & 7);
    int lkb   = ((lane >> 3) & 1) * 8;

    uint32_t qf[4][2][4];
    {
        const uint32_t* qu = (const uint32_t*)Q;
        #pragma unroll
        for (int mf = 0; mf < 2; mf++) {
            int r = qb + warp * 32 + mf * 16 + g4;
            size_t base0 = (size_t)r * (MIDW / 2) + (hoff >> 1);
            size_t base1 = base0 + 8 * (MIDW / 2);
            #pragma unroll
            for (int ks = 0; ks < 4; ks++) {
                qf[ks][mf][0] = qu[base0 + ks * 8 + t4];
                qf[ks][mf][1] = qu[base1 + ks * 8 + t4];
                qf[ks][mf][2] = qu[base0 + ks * 8 + t4 + 4];
                qf[ks][mf][3] = qu[base1 + ks * 8 + t4 + 4];
            }
        }
    }

    float o[2][8][4];
    #pragma unroll
    for (int mf = 0; mf < 2; mf++)
        #pragma unroll
        for (int i = 0; i < 8; i++)
            #pragma unroll
            for (int j = 0; j < 4; j++) o[mf][i][j] = 0.f;
    float lr[2][2] = {{0.f, 0.f}, {0.f, 0.f}};

    auto loadKV = [&](int mt, int bufi) {
        int kb = kvb + mt * 64;
        __half* ks = Ks + bufi * 64 * KST;
        __half* vs = Vs + bufi * 64 * KST;
        #pragma unroll
        for (int i = 0; i < 8; i++) {
            int c = tid + i * 128;
            int key = c >> 4, seg = c & 15;
            const __half* row = KV + (size_t)(kb + key) * (2 * MIDW);
            if (seg < 8) cp16(ks + key * KST + seg * 8, row + hoff + seg * 8);
            else         cp16(vs + key * KST + (seg - 8) * 8, row + MIDW + hoff + (seg - 8) * 8);
        }
    };

    int nt = m_len >> 6;
    loadKV(0, 0); cp_commit();
    int buf = 0;
    for (int mt = 0; mt < nt; mt++) {
        if (mt + 1 < nt) { loadKV(mt + 1, buf ^ 1); cp_commit(); cp_wait1(); }
        else             { cp_wait0(); }
        __syncthreads();
        const __half* ksb = Ks + buf * 64 * KST;
        const __half* vsb = Vs + buf * 64 * KST;

        float sa[2][8][4];
        #pragma unroll
        for (int mf = 0; mf < 2; mf++)
            #pragma unroll
            for (int i = 0; i < 8; i++)
                #pragma unroll
                for (int j = 0; j < 4; j++) sa[mf][i][j] = 0.f;
        #pragma unroll
        for (int ks = 0; ks < 4; ks++) {
            #pragma unroll
            for (int nf2 = 0; nf2 < 4; nf2++) {
                uint32_t bb[4];
                ldsm_x4(bb, ksb + (nf2 * 16 + lrowK) * KST + ks * 16 + lkb);
                uint32_t b0[2] = { bb[0], bb[1] };
                uint32_t b1[2] = { bb[2], bb[3] };
                #pragma unroll
                for (int mf = 0; mf < 2; mf++) {
                    mma16(sa[mf][nf2 * 2],     qf[ks][mf], b0);
                    mma16(sa[mf][nf2 * 2 + 1], qf[ks][mf], b1);
                }
            }
        }

        uint32_t pf[4][2][4];
        #pragma unroll
        for (int mf = 0; mf < 2; mf++) {
            float s0 = 0.f, s1 = 0.f;
            #pragma unroll
            for (int kb2 = 0; kb2 < 4; kb2++) {
                float p00 = ex2f(sa[mf][2*kb2][0]),   p01 = ex2f(sa[mf][2*kb2][1]);
                float p02 = ex2f(sa[mf][2*kb2][2]),   p03 = ex2f(sa[mf][2*kb2][3]);
                float p10 = ex2f(sa[mf][2*kb2+1][0]), p11 = ex2f(sa[mf][2*kb2+1][1]);
                float p12 = ex2f(sa[mf][2*kb2+1][2]), p13 = ex2f(sa[mf][2*kb2+1][3]);
                s0 += p00 + p01 + p10 + p11;
                s1 += p02 + p03 + p12 + p13;
                pf[kb2][mf][0] = packh(p00, p01);
                pf[kb2][mf][1] = packh(p02, p03);
                pf[kb2][mf][2] = packh(p10, p11);
                pf[kb2][mf][3] = packh(p12, p13);
            }
            lr[mf][0] += s0; lr[mf][1] += s1;
        }

        #pragma unroll
        for (int kb2 = 0; kb2 < 4; kb2++) {
            #pragma unroll
            for (int nf2 = 0; nf2 < 4; nf2++) {
                uint32_t vreg[4];
                int vrow = kb2 * 16 + ((lane >> 3) & 1) * 8 + (lane & 7);
                int vcol = nf2 * 16 + (lane >> 4) * 8;
                ldsm_x4_trans(vreg, vsb + vrow * KST + vcol);
                uint32_t b0[2] = { vreg[0], vreg[1] };
                uint32_t b1[2] = { vreg[2], vreg[3] };
                #pragma unroll
                for (int mf = 0; mf < 2; mf++) {
                    mma16(o[mf][nf2 * 2],     pf[kb2][mf], b0);
                    mma16(o[mf][nf2 * 2 + 1], pf[kb2][mf], b1);
                }
            }
        }
        __syncthreads();
        buf ^= 1;
    }

    uint32_t* Ou = (uint32_t*)O;
    #pragma unroll
    for (int mf = 0; mf < 2; mf++) {
        float l0 = lr[mf][0], l1 = lr[mf][1];
        l0 += __shfl_xor_sync(0xffffffffu, l0, 1);
        l0 += __shfl_xor_sync(0xffffffffu, l0, 2);
        l1 += __shfl_xor_sync(0xffffffffu, l1, 1);
        l1 += __shfl_xor_sync(0xffffffffu, l1, 2);
        float inv0 = 1.f / l0, inv1 = 1.f / l1;
        int r = qb + warp * 32 + mf * 16 + g4;
        size_t ob0 = (size_t)r * (MIDW / 2) + (hoff >> 1);
        size_t ob1 = ob0 + 8 * (MIDW / 2);
        #pragma unroll
        for (int nf = 0; nf < 8; nf++) {
            int ci = nf * 4 + t4;
            Ou[ob0 + ci] = packh(o[mf][nf][0] * inv0, o[mf][nf][1] * inv0);
            Ou[ob1 + ci] = packh(o[mf][nf][2] * inv1, o[mf][nf][3] * inv1);
        }
    }
}

// ---------------------------------------------------------------------------
// Launch
// ---------------------------------------------------------------------------
extern "C" void kernel_launch(void* const* d_in, const int* in_sizes, int n_in,
                              void* d_out, int out_size) {
    const float* x      = (const float*)d_in[0];
    const float* ctx    = (const float*)d_in[1];
    const float* sa_ng  = (const float*)d_in[2];
    const float* sa_nb  = (const float*)d_in[3];
    const float* sa_ncg = (const float*)d_in[4];
    const float* sa_ncb = (const float*)d_in[5];
    const float* sa_wq  = (const float*)d_in[6];
    const float* sa_wkv = (const float*)d_in[7];
    const float* sa_wo  = (const float*)d_in[8];
    const float* sa_bo  = (const float*)d_in[9];
    const float* ca_ng  = (const float*)d_in[10];
    const float* ca_nb  = (const float*)d_in[11];
    const float* ca_ncg = (const float*)d_in[12];
    const float* ca_ncb = (const float*)d_in[13];
    const float* ca_wq  = (const float*)d_in[14];
    const float* ca_wkv = (const float*)d_in[15];
    const float* ca_wo  = (const float*)d_in[16];
    const float* ca_bo  = (const float*)d_in[17];
    float* out = (float*)d_out;

    __half *xn, *cx, *q, *kv, *ao, *wt;
    float* nb;
    cudaGetSymbolAddress((void**)&xn, g_xn);
    cudaGetSymbolAddress((void**)&cx, g_cx);
    cudaGetSymbolAddress((void**)&q,  g_q);
    cudaGetSymbolAddress((void**)&kv, g_kv);
    cudaGetSymbolAddress((void**)&ao, g_ao);
    cudaGetSymbolAddress((void**)&wt, g_wt);
    cudaGetSymbolAddress((void**)&nb, g_nb);

    static bool inited = false;
    static cudaStream_t s1, s2;
    static cudaEvent_t eFork, eW1, eW2, eC, eLN, eB1, eF1, eKV2;
    if (!inited) {
        cudaStreamCreateWithFlags(&s1, cudaStreamNonBlocking);
        cudaStreamCreateWithFlags(&s2, cudaStreamNonBlocking);
        cudaEventCreateWithFlags(&eFork, cudaEventDisableTiming);
        cudaEventCreateWithFlags(&eW1, cudaEventDisableTiming);
        cudaEventCreateWithFlags(&eW2, cudaEventDisableTiming);
        cudaEventCreateWithFlags(&eC,  cudaEventDisableTiming);
        cudaEventCreateWithFlags(&eLN, cudaEventDisableTiming);
        cudaEventCreateWithFlags(&eB1, cudaEventDisableTiming);
        cudaEventCreateWithFlags(&eF1, cudaEventDisableTiming);
        cudaEventCreateWithFlags(&eKV2, cudaEventDisableTiming);
        cudaFuncSetAttribute(gemm_fp16, cudaFuncAttributeMaxDynamicSharedMemorySize, GEMM_SMEM);
        cudaFuncSetAttribute(gemm_qkv,  cudaFuncAttributeMaxDynamicSharedMemorySize, GEMM_SMEM);
        cudaFuncSetAttribute(flash_fp16, cudaFuncAttributeMaxDynamicSharedMemorySize, FL_SMEM);
        inited = true;
    }

    dim3 tb(32, 8);

    cudaEventRecord(eFork, 0);
    cudaStreamWaitEvent(s1, eFork, 0);
    cudaStreamWaitEvent(s2, eFork, 0);

    // Phase A: plain LN(x) on s0 | sa weight prep on s1 | sa bias vectors on s2
    ln_plain<<<ROWS, 256>>>(x, xn, FF);
    cudaEventRecord(eLN, 0);

    wtrans_kernel<<<dim3(MIDW/32, FF/32),   tb, 0, s1>>>(sa_wq,  wt + OFF_SA_WQ,  FF, MIDW, sa_ng, QK_SCALE);
    wtrans_kernel<<<dim3(2*MIDW/32, FF/32), tb, 0, s1>>>(sa_wkv, wt + OFF_SA_WKV, FF, 2*MIDW, sa_ncg, 1.f);
    cudaEventRecord(eW1, s1);

    bvec_kernel<<<MIDW/64, 512, 0, s2>>>(sa_nb,  sa_wq,  nb + NB_SA,       FF, MIDW,   QK_SCALE);
    bvec_kernel<<<2*MIDW/64, 512, 0, s2>>>(sa_ncb, sa_wkv, nb + NB_SA + 512, FF, 2*MIDW, 1.f);
    cudaEventRecord(eB1, s2);

    // Phase B: merged QKV gemm (768 CTAs) on s0
    cudaStreamWaitEvent(0, eW1, 0);
    cudaStreamWaitEvent(0, eB1, 0);
    gemm_qkv<<<dim3(1536/128, ROWS/128), 128, GEMM_SMEM>>>(
        xn, wt + OFF_SA_WQ, q, kv, ROWS, FF, nb + NB_SA);

    // Phase C: flash-sa on s0
    flash_fp16<<<dim3(NQ/128, BB*HH), 128, FL_SMEM>>>(q, kv, ao, NQ);
    cudaEventRecord(eF1, 0);

    // overlap flash: remaining weight prep on s1, ca biases + ctx LN on s2
    wtrans_kernel<<<dim3(FF/32, MIDW/32),   tb, 0, s1>>>(sa_wo,  wt + OFF_SA_WO,  MIDW, FF, nullptr, 1.f);
    wtrans_kernel<<<dim3(MIDW/32, FF/32),   tb, 0, s1>>>(ca_wq,  wt + OFF_CA_WQ,  FF, MIDW, ca_ng, QK_SCALE);
    wtrans_kernel<<<dim3(2*MIDW/32, CFF/32),tb, 0, s1>>>(ca_wkv, wt + OFF_CA_WKV, CFF, 2*MIDW, ca_ncg, 1.f);
    wtrans_kernel<<<dim3(FF/32, MIDW/32),   tb, 0, s1>>>(ca_wo,  wt + OFF_CA_WO,  MIDW, FF, nullptr, 1.f);
    cudaEventRecord(eW2, s1);

    bvec_kernel<<<MIDW/64, 512, 0, s2>>>(ca_nb,  ca_wq,  nb + NB_CA_Q,  FF,  MIDW,   QK_SCALE);
    bvec_kernel<<<2*MIDW/64, 512, 0, s2>>>(ca_ncb, ca_wkv, nb + NB_CA_KV, CFF, 2*MIDW, 1.f);
    ln_plain<<<CROWS, 256, 0, s2>>>(ctx, cx, CFF);
    cudaEventRecord(eC, s2);

    // Phase D: WO-gemm-sa on s0 (fp32 out + bias + residual x)
    cudaStreamWaitEvent(0, eW2, 0);
    gemm_fp16<<<dim3(FF/128, ROWS/128), 128, GEMM_SMEM>>>(
        ao, wt + OFF_SA_WO, out, ROWS, FF, MIDW, sa_bo, x, 0, nullptr);

    // Phase E: LN(out) + Q-gemm-ca on s0
    ln_plain<<<ROWS, 256>>>(out, xn, FF);
    cudaStreamWaitEvent(0, eC, 0);
    gemm_fp16<<<dim3(MIDW/128, ROWS/128), 128, GEMM_SMEM>>>(
        xn, wt + OFF_CA_WQ, q, ROWS, MIDW, FF, nullptr, nullptr, 1, nb + NB_CA_Q);

    // Phase F: KV-gemm-ca on s1 (after flash-sa frees kv; ctx LN + biases done)
    cudaStreamWaitEvent(s1, eF1, 0);
    cudaStreamWaitEvent(s1, eC, 0);
    gemm_fp16<<<dim3(2*MIDW/128, CROWS/128), 128, GEMM_SMEM, s1>>>(
        cx, wt + OFF_CA_WKV, kv, CROWS, 2*MIDW, CFF, nullptr, nullptr, 1, nb + NB_CA_KV);
    cudaEventRecord(eKV2, s1);

    // Phase G: flash-ca + WO-gemm-ca on s0
    cudaStreamWaitEvent(0, eKV2, 0);
    flash_fp16<<<dim3(NQ/128, BB*HH), 128, FL_SMEM>>>(q, kv, ao, 512);
    gemm_fp16<<<dim3(FF/128, ROWS/128), 128, GEMM_SMEM>>>(
        ao, wt + OFF_CA_WO, out, ROWS, FF, MIDW, ca_bo, out, 0, nullptr);
}

// round 15
// speedup vs baseline: 1.3676x; 1.0617x over previous
#include <cuda_runtime.h>
#include <cuda_fp16.h>
#include <math.h>
#include <stdint.h>

#define BB 4
#define NQ 2048
#define FF 1024
#define CFF 768
#define HH 8
#define DD 64
#define MIDW 512
#define ROWS (BB*NQ)        // 8192
#define CROWS (BB*512)      // 2048
#define QK_SCALE (0.125f * 1.4426950408889634f)

// Scratch (device globals, fp16 activations)
__device__ __half g_xn[ROWS*FF];
__device__ __half g_cx[CROWS*CFF];
__device__ __half g_q [ROWS*MIDW];
__device__ __half g_kv[ROWS*2*MIDW];
__device__ __half g_ao[ROWS*MIDW];
__device__ __half g_wt[4*1024*1024];
__device__ float  g_nb[4096];          // folded LN-bias column vectors
__device__ float  g_nbp[8*1024];       // bvec partials

#define OFF_SA_WQ  0
#define OFF_SA_WKV 524288
#define OFF_SA_WO  1572864
#define OFF_CA_WQ  2097152
#define OFF_CA_WKV 2621440
#define OFF_CA_WO  3407872
#define NB_SA   0
#define NB_CA_Q 2048
#define NB_CA_KV 2560

// ---------------------------------------------------------------------------
// helpers
// ---------------------------------------------------------------------------
__device__ __forceinline__ void cp16(void* dst, const void* src) {
    uint32_t d = (uint32_t)__cvta_generic_to_shared(dst);
    asm volatile("cp.async.cg.shared.global [%0], [%1], 16;\n" :: "r"(d), "l"(src));
}
__device__ __forceinline__ void cp_commit() { asm volatile("cp.async.commit_group;\n" ::: "memory"); }
__device__ __forceinline__ void cp_wait0()  { asm volatile("cp.async.wait_group 0;\n" ::: "memory"); }
__device__ __forceinline__ void cp_wait1()  { asm volatile("cp.async.wait_group 1;\n" ::: "memory"); }

__device__ __forceinline__ void mma16(float (&d)[4], const uint32_t (&a)[4],
                                      const uint32_t (&b)[2]) {
    asm volatile(
        "mma.sync.aligned.m16n8k16.row.col.f32.f16.f16.f32 "
        "{%0,%1,%2,%3},{%4,%5,%6,%7},{%8,%9},{%0,%1,%2,%3};\n"
        : "+f"(d[0]), "+f"(d[1]), "+f"(d[2]), "+f"(d[3])
        : "r"(a[0]), "r"(a[1]), "r"(a[2]), "r"(a[3]), "r"(b[0]), "r"(b[1]));
}
__device__ __forceinline__ uint32_t packh(float lo, float hi) {
    uint32_t r;
    asm("cvt.rn.f16x2.f32 %0, %1, %2;\n" : "=r"(r) : "f"(hi), "f"(lo));
    return r;
}
__device__ __forceinline__ float ex2f(float x) {
    float y; asm("ex2.approx.f32 %0, %1;\n" : "=f"(y) : "f"(x)); return y;
}
__device__ __forceinline__ void ldsm_x4(uint32_t (&r)[4], const void* p) {
    uint32_t a = (uint32_t)__cvta_generic_to_shared(p);
    asm volatile("ldmatrix.sync.aligned.m8n8.x4.shared.b16 {%0,%1,%2,%3}, [%4];\n"
                 : "=r"(r[0]), "=r"(r[1]), "=r"(r[2]), "=r"(r[3]) : "r"(a));
}
__device__ __forceinline__ void ldsm_x4_trans(uint32_t (&r)[4], const void* p) {
    uint32_t a = (uint32_t)__cvta_generic_to_shared(p);
    asm volatile("ldmatrix.sync.aligned.m8n8.x4.trans.shared.b16 {%0,%1,%2,%3}, [%4];\n"
                 : "=r"(r[0]), "=r"(r[1]), "=r"(r[2]), "=r"(r[3]) : "r"(a));
}

// ---------------------------------------------------------------------------
// Weight transpose + gain-fold + scale: fp32 [K][N] -> fp16 [N][K]
// ---------------------------------------------------------------------------
__global__ void wtrans_kernel(const float* __restrict__ in, __half* __restrict__ out,
                              int K, int N, const float* __restrict__ gain, float scale) {
    __shared__ float t[32][33];
    int n0 = blockIdx.x * 32, k0 = blockIdx.y * 32;
    int tx = threadIdx.x, ty = threadIdx.y;
    #pragma unroll
    for (int i = 0; i < 4; i++)
        t[ty + i * 8][tx] = in[(size_t)(k0 + ty + i * 8) * N + n0 + tx];
    __syncthreads();
    float gk = (gain ? gain[k0 + tx] : 1.f) * scale;
    #pragma unroll
    for (int i = 0; i < 4; i++)
        out[(size_t)(n0 + ty + i * 8) * K + k0 + tx] = __float2half(t[tx][ty + i * 8] * gk);
}

// bvec partial: grid (N/64, 8); block 256 = 64 cols x 4 sub-slices.
// partial[y][col] = scale * sum_{k in slice y} b[k]*w[k][col]
__global__ __launch_bounds__(256) void bvec_partial(
    const float* __restrict__ b, const float* __restrict__ w,
    float* __restrict__ partial, int K, int N, float scale)
{
    __shared__ float red[256];
    int col = blockIdx.x * 64 + (threadIdx.x & 63);
    int sub = threadIdx.x >> 6;            // 0..3
    int kseg = K >> 3;                     // rows per blockIdx.y
    int ksub = kseg >> 2;                  // rows per sub-slice
    int k0 = blockIdx.y * kseg + sub * ksub;
    float s = 0.f;
    #pragma unroll 4
    for (int k = k0; k < k0 + ksub; k++)
        s += b[k] * w[(size_t)k * N + col];
    red[threadIdx.x] = s;
    __syncthreads();
    if (threadIdx.x < 64) {
        float t = red[threadIdx.x] + red[64 + threadIdx.x]
                + red[128 + threadIdx.x] + red[192 + threadIdx.x];
        partial[blockIdx.y * N + col] = t * scale;
    }
}
// combine 8 partials
__global__ void bvec_combine(const float* __restrict__ partial, float* __restrict__ out, int N) {
    int n = blockIdx.x * 256 + threadIdx.x;
    if (n < N) {
        float s = 0.f;
        #pragma unroll
        for (int i = 0; i < 8; i++) s += partial[i * N + n];
        out[n] = s;
    }
}

// ---------------------------------------------------------------------------
// Plain LayerNorm (gain/bias folded into weights): fp32 -> fp16
// ---------------------------------------------------------------------------
__device__ __forceinline__ void ln_stats(const float* x, int C, int tid, int bdim,
                                         float& mean, float& inv) {
    float s = 0.f, s2 = 0.f;
    for (int i = tid; i < (C >> 2); i += bdim) {
        float4 v = *(const float4*)&x[4 * i];
        s  += v.x + v.y + v.z + v.w;
        s2 += v.x * v.x + v.y * v.y + v.z * v.z + v.w * v.w;
    }
    __shared__ float red[64];
    #pragma unroll
    for (int off = 16; off > 0; off >>= 1) {
        s  += __shfl_down_sync(0xffffffffu, s, off);
        s2 += __shfl_down_sync(0xffffffffu, s2, off);
    }
    int wid = tid >> 5, lid = tid & 31;
    if (lid == 0) { red[wid] = s; red[wid + 32] = s2; }
    __syncthreads();
    if (wid == 0) {
        int nw = bdim >> 5;
        s  = (lid < nw) ? red[lid] : 0.f;
        s2 = (lid < nw) ? red[lid + 32] : 0.f;
        #pragma unroll
        for (int off = 16; off > 0; off >>= 1) {
            s  += __shfl_down_sync(0xffffffffu, s, off);
            s2 += __shfl_down_sync(0xffffffffu, s2, off);
        }
        if (lid == 0) { red[0] = s; red[1] = s2; }
    }
    __syncthreads();
    mean = red[0] / C;
    float var = red[1] / C - mean * mean;
    inv = rsqrtf(var + 1e-5f);
}

__global__ void ln_plain(const float* __restrict__ in, __half* __restrict__ out, int C) {
    int row = blockIdx.x;
    const float* x = in + (size_t)row * C;
    uint32_t* o = (uint32_t*)(out + (size_t)row * C);
    float mean, inv;
    ln_stats(x, C, threadIdx.x, blockDim.x, mean, inv);
    for (int i = threadIdx.x; i < (C >> 1); i += blockDim.x) {
        float2 xv = *(const float2*)&x[2 * i];
        o[i] = packh((xv.x - mean) * inv, (xv.y - mean) * inv);
    }
}

// ---------------------------------------------------------------------------
// FP16 GEMM (R11-verified): 128x128 CTA, 128 threads, 4 warps 2x2, warp 64x64.
// ---------------------------------------------------------------------------
#define GKS 72
#define GEMM_SMEM (2*2*128*GKS*2)

__global__ __launch_bounds__(128) void gemm_fp16(
    const __half* __restrict__ A, const __half* __restrict__ Bt,
    void* __restrict__ Cout, int M, int N, int K,
    const float* __restrict__ bias, const float* __restrict__ res, int outbf,
    const float* __restrict__ nbias)
{
    extern __shared__ __half smh[];
    __half* As = smh;
    __half* Bs = smh + 2 * 128 * GKS;
    int tid = threadIdx.x, lane = tid & 31, warp = tid >> 5;
    int t4 = lane & 3, g4 = lane >> 2;
    int wm = warp >> 1, wn = warp & 1;
    int m0 = blockIdx.y * 128, n0 = blockIdx.x * 128;

    int lrowA = ((lane >> 3) & 1) * 8 + (lane & 7);
    int lka   = (lane >> 4) * 8;
    int lrowB = (lane >> 4) * 8 + (lane & 7);
    int lkb   = ((lane >> 3) & 1) * 8;

    float acc[4][8][4];
    #pragma unroll
    for (int i = 0; i < 4; i++)
        #pragma unroll
        for (int j = 0; j < 8; j++)
            #pragma unroll
            for (int k = 0; k < 4; k++) acc[i][j][k] = 0.f;

    auto loadTile = [&](int kt, int s) {
        int k0 = kt * 64;
        __half* as = As + s * 128 * GKS;
        __half* bs = Bs + s * 128 * GKS;
        #pragma unroll
        for (int i = 0; i < 8; i++) {
            int c = tid + i * 128;
            int m = c >> 3, seg = c & 7;
            cp16(as + m * GKS + seg * 8, A + (size_t)(m0 + m) * K + k0 + seg * 8);
        }
        #pragma unroll
        for (int i = 0; i < 8; i++) {
            int c = tid + i * 128;
            int n = c >> 3, seg = c & 7;
            cp16(bs + n * GKS + seg * 8, Bt + (size_t)(n0 + n) * K + k0 + seg * 8);
        }
    };

    int nIter = K >> 6;
    loadTile(0, 0); cp_commit();
    int buf = 0;
    for (int kt = 0; kt < nIter; kt++) {
        if (kt + 1 < nIter) { loadTile(kt + 1, buf ^ 1); cp_commit(); cp_wait1(); }
        else                { cp_wait0(); }
        __syncthreads();
        const __half* as = As + buf * 128 * GKS;
        const __half* bs = Bs + buf * 128 * GKS;
        #pragma unroll
        for (int ks = 0; ks < 4; ks++) {
            uint32_t af[4][4];
            #pragma unroll
            for (int mf = 0; mf < 4; mf++)
                ldsm_x4(af[mf], as + (wm * 64 + mf * 16 + lrowA) * GKS + ks * 16 + lka);
            #pragma unroll
            for (int nf2 = 0; nf2 < 4; nf2++) {
                uint32_t bb[4];
                ldsm_x4(bb, bs + (wn * 64 + nf2 * 16 + lrowB) * GKS + ks * 16 + lkb);
                uint32_t b0[2] = { bb[0], bb[1] };
                uint32_t b1[2] = { bb[2], bb[3] };
                #pragma unroll
                for (int mf = 0; mf < 4; mf++) {
                    mma16(acc[mf][nf2 * 2],     af[mf], b0);
                    mma16(acc[mf][nf2 * 2 + 1], af[mf], b1);
                }
            }
        }
        __syncthreads();
        buf ^= 1;
    }

    if (outbf) {
        uint32_t* C2 = (uint32_t*)Cout;
        int N2 = N >> 1;
        #pragma unroll
        for (int mf = 0; mf < 4; mf++) {
            #pragma unroll
            for (int nf = 0; nf < 8; nf++) {
                int r  = m0 + wm * 64 + mf * 16 + g4;
                int cc = n0 + wn * 64 + nf * 8 + 2 * t4;
                float a0 = acc[mf][nf][0], a1 = acc[mf][nf][1];
                float a2 = acc[mf][nf][2], a3 = acc[mf][nf][3];
                if (nbias) {
                    float2 nb = *(const float2*)&nbias[cc];
                    a0 += nb.x; a1 += nb.y; a2 += nb.x; a3 += nb.y;
                }
                C2[(size_t)r * N2 + (cc >> 1)]       = packh(a0, a1);
                C2[(size_t)(r + 8) * N2 + (cc >> 1)] = packh(a2, a3);
            }
        }
    } else {
        float* C = (float*)Cout;
        #pragma unroll
        for (int mf = 0; mf < 4; mf++) {
            #pragma unroll
            for (int nf = 0; nf < 8; nf++) {
                int r  = m0 + wm * 64 + mf * 16 + g4;
                int cc = n0 + wn * 64 + nf * 8 + 2 * t4;
                float2 v0 = make_float2(acc[mf][nf][0], acc[mf][nf][1]);
                float2 v1 = make_float2(acc[mf][nf][2], acc[mf][nf][3]);
                float2 bv = *(const float2*)&bias[cc];
                v0.x += bv.x; v0.y += bv.y; v1.x += bv.x; v1.y += bv.y;
                float2 r0 = *(const float2*)&res[(size_t)r * N + cc];
                float2 r1 = *(const float2*)&res[(size_t)(r + 8) * N + cc];
                v0.x += r0.x; v0.y += r0.y; v1.x += r1.x; v1.y += r1.y;
                *(float2*)&C[(size_t)r * N + cc] = v0;
                *(float2*)&C[(size_t)(r + 8) * N + cc] = v1;
            }
        }
    }
}

// ---------------------------------------------------------------------------
// Merged QKV GEMM (self-attn): split epilogue Q/KV. Verified mainloop.
// ---------------------------------------------------------------------------
__global__ __launch_bounds__(128) void gemm_qkv(
    const __half* __restrict__ A, const __half* __restrict__ Bt,
    __half* __restrict__ Qo, __half* __restrict__ KVo, int M, int K,
    const float* __restrict__ nbias)
{
    extern __shared__ __half smh[];
    __half* As = smh;
    __half* Bs = smh + 2 * 128 * GKS;
    int tid = threadIdx.x, lane = tid & 31, warp = tid >> 5;
    int t4 = lane & 3, g4 = lane >> 2;
    int wm = warp >> 1, wn = warp & 1;
    int m0 = blockIdx.y * 128, n0 = blockIdx.x * 128;

    int lrowA = ((lane >> 3) & 1) * 8 + (lane & 7);
    int lka   = (lane >> 4) * 8;
    int lrowB = (lane >> 4) * 8 + (lane & 7);
    int lkb   = ((lane >> 3) & 1) * 8;

    float acc[4][8][4];
    #pragma unroll
    for (int i = 0; i < 4; i++)
        #pragma unroll
        for (int j = 0; j < 8; j++)
            #pragma unroll
            for (int k = 0; k < 4; k++) acc[i][j][k] = 0.f;

    auto loadTile = [&](int kt, int s) {
        int k0 = kt * 64;
        __half* as = As + s * 128 * GKS;
        __half* bs = Bs + s * 128 * GKS;
        #pragma unroll
        for (int i = 0; i < 8; i++) {
            int c = tid + i * 128;
            int m = c >> 3, seg = c & 7;
            cp16(as + m * GKS + seg * 8, A + (size_t)(m0 + m) * K + k0 + seg * 8);
        }
        #pragma unroll
        for (int i = 0; i < 8; i++) {
            int c = tid + i * 128;
            int n = c >> 3, seg = c & 7;
            cp16(bs + n * GKS + seg * 8, Bt + (size_t)(n0 + n) * K + k0 + seg * 8);
        }
    };

    int nIter = K >> 6;
    loadTile(0, 0); cp_commit();
    int buf = 0;
    for (int kt = 0; kt < nIter; kt++) {
        if (kt + 1 < nIter) { loadTile(kt + 1, buf ^ 1); cp_commit(); cp_wait1(); }
        else                { cp_wait0(); }
        __syncthreads();
        const __half* as = As + buf * 128 * GKS;
        const __half* bs = Bs + buf * 128 * GKS;
        #pragma unroll
        for (int ks = 0; ks < 4; ks++) {
            uint32_t af[4][4];
            #pragma unroll
            for (int mf = 0; mf < 4; mf++)
                ldsm_x4(af[mf], as + (wm * 64 + mf * 16 + lrowA) * GKS + ks * 16 + lka);
            #pragma unroll
            for (int nf2 = 0; nf2 < 4; nf2++) {
                uint32_t bb[4];
                ldsm_x4(bb, bs + (wn * 64 + nf2 * 16 + lrowB) * GKS + ks * 16 + lkb);
                uint32_t b0[2] = { bb[0], bb[1] };
                uint32_t b1[2] = { bb[2], bb[3] };
                #pragma unroll
                for (int mf = 0; mf < 4; mf++) {
                    mma16(acc[mf][nf2 * 2],     af[mf], b0);
                    mma16(acc[mf][nf2 * 2 + 1], af[mf], b1);
                }
            }
        }
        __syncthreads();
        buf ^= 1;
    }

    uint32_t* C2 = (n0 < 512) ? (uint32_t*)Qo : (uint32_t*)KVo;
    int N2      = (n0 < 512) ? (MIDW >> 1)    : MIDW;
    int coff    = (n0 < 512) ? 0              : 512;
    #pragma unroll
    for (int mf = 0; mf < 4; mf++) {
        #pragma unroll
        for (int nf = 0; nf < 8; nf++) {
            int r  = m0 + wm * 64 + mf * 16 + g4;
            int cc = n0 + wn * 64 + nf * 8 + 2 * t4;
            float2 nb = *(const float2*)&nbias[cc];
            float a0 = acc[mf][nf][0] + nb.x, a1 = acc[mf][nf][1] + nb.y;
            float a2 = acc[mf][nf][2] + nb.x, a3 = acc[mf][nf][3] + nb.y;
            int cl = cc - coff;
            C2[(size_t)r * N2 + (cl >> 1)]       = packh(a0, a1);
            C2[(size_t)(r + 8) * N2 + (cl >> 1)] = packh(a2, a3);
        }
    }
}

// ---------------------------------------------------------------------------
// FP16 flash (R11-verified): 128 threads, 4 warps x 32 rows, max-free softmax
// ---------------------------------------------------------------------------
#define KST 72
#define FL_SMEM (2*(64*KST + 64*KST)*2)

__global__ __launch_bounds__(128) void flash_fp16(
    const __half* __restrict__ Q, const __half* __restrict__ KV,
    __half* __restrict__ O, int m_len)
{
    extern __shared__ __half fsm[];
    __half* Ks = fsm;
    __half* Vs = fsm + 2 * 64 * KST;
    int tid = threadIdx.x, lane = tid & 31, warp = tid >> 5;
    int t4 = lane & 3, g4 = lane >> 2;
    int bh = blockIdx.y, b = bh >> 3, h = bh & 7;
    int hoff = h * DD;
    int qb = b * NQ + blockIdx.x * 128;
    int kvb = b * m_len;

    int lrowK = ((lane >> 4) & 1) * 8 + (lane & 7);
    int lkb   = ((lane >> 3) & 1) * 8;

    uint32_t qf[4][2][4];
    {
        const uint32_t* qu = (const uint32_t*)Q;
        #pragma unroll
        for (int mf = 0; mf < 2; mf++) {
            int r = qb + warp * 32 + mf * 16 + g4;
            size_t base0 = (size_t)r * (MIDW / 2) + (hoff >> 1);
            size_t base1 = base0 + 8 * (MIDW / 2);
            #pragma unroll
            for (int ks = 0; ks < 4; ks++) {
                qf[ks][mf][0] = qu[base0 + ks * 8 + t4];
                qf[ks][mf][1] = qu[base1 + ks * 8 + t4];
                qf[ks][mf][2] = qu[base0 + ks * 8 + t4 + 4];
                qf[ks][mf][3] = qu[base1 + ks * 8 + t4 + 4];
            }
        }
    }

    float o[2][8][4];
    #pragma unroll
    for (int mf = 0; mf < 2; mf++)
        #pragma unroll
        for (int i = 0; i < 8; i++)
            #pragma unroll
            for (int j = 0; j < 4; j++) o[mf][i][j] = 0.f;
    float lr[2][2] = {{0.f, 0.f}, {0.f, 0.f}};

    auto loadKV = [&](int mt, int bufi) {
        int kb = kvb + mt * 64;
        __half* ks = Ks + bufi * 64 * KST;
        __half* vs = Vs + bufi * 64 * KST;
        #pragma unroll
        for (int i = 0; i < 8; i++) {
            int c = tid + i * 128;
            int key = c >> 4, seg = c & 15;
            const __half* row = KV + (size_t)(kb + key) * (2 * MIDW);
            if (seg < 8) cp16(ks + key * KST + seg * 8, row + hoff + seg * 8);
            else         cp16(vs + key * KST + (seg - 8) * 8, row + MIDW + hoff + (seg - 8) * 8);
        }
    };

    int nt = m_len >> 6;
    loadKV(0, 0); cp_commit();
    int buf = 0;
    for (int mt = 0; mt < nt; mt++) {
        if (mt + 1 < nt) { loadKV(mt + 1, buf ^ 1); cp_commit(); cp_wait1(); }
        else             { cp_wait0(); }
        __syncthreads();
        const __half* ksb = Ks + buf * 64 * KST;
        const __half* vsb = Vs + buf * 64 * KST;

        float sa[2][8][4];
        #pragma unroll
        for (int mf = 0; mf < 2; mf++)
            #pragma unroll
            for (int i = 0; i < 8; i++)
                #pragma unroll
                for (int j = 0; j < 4; j++) sa[mf][i][j] = 0.f;
        #pragma unroll
        for (int ks = 0; ks < 4; ks++) {
            #pragma unroll
            for (int nf2 = 0; nf2 < 4; nf2++) {
                uint32_t bb[4];
                ldsm_x4(bb, ksb + (nf2 * 16 + lrowK) * KST + ks * 16 + lkb);
                uint32_t b0[2] = { bb[0], bb[1] };
                uint32_t b1[2] = { bb[2], bb[3] };
                #pragma unroll
                for (int mf = 0; mf < 2; mf++) {
                    mma16(sa[mf][nf2 * 2],     qf[ks][mf], b0);
                    mma16(sa[mf][nf2 * 2 + 1], qf[ks][mf], b1);
                }
            }
        }

        uint32_t pf[4][2][4];
        #pragma unroll
        for (int mf = 0; mf < 2; mf++) {
            float s0 = 0.f, s1 = 0.f;
            #pragma unroll
            for (int kb2 = 0; kb2 < 4; kb2++) {
                float p00 = ex2f(sa[mf][2*kb2][0]),   p01 = ex2f(sa[mf][2*kb2][1]);
                float p02 = ex2f(sa[mf][2*kb2][2]),   p03 = ex2f(sa[mf][2*kb2][3]);
                float p10 = ex2f(sa[mf][2*kb2+1][0]), p11 = ex2f(sa[mf][2*kb2+1][1]);
                float p12 = ex2f(sa[mf][2*kb2+1][2]), p13 = ex2f(sa[mf][2*kb2+1][3]);
                s0 += p00 + p01 + p10 + p11;
                s1 += p02 + p03 + p12 + p13;
                pf[kb2][mf][0] = packh(p00, p01);
                pf[kb2][mf][1] = packh(p02, p03);
                pf[kb2][mf][2] = packh(p10, p11);
                pf[kb2][mf][3] = packh(p12, p13);
            }
            lr[mf][0] += s0; lr[mf][1] += s1;
        }

        #pragma unroll
        for (int kb2 = 0; kb2 < 4; kb2++) {
            #pragma unroll
            for (int nf2 = 0; nf2 < 4; nf2++) {
                uint32_t vreg[4];
                int vrow = kb2 * 16 + ((lane >> 3) & 1) * 8 + (lane & 7);
                int vcol = nf2 * 16 + (lane >> 4) * 8;
                ldsm_x4_trans(vreg, vsb + vrow * KST + vcol);
                uint32_t b0[2] = { vreg[0], vreg[1] };
                uint32_t b1[2] = { vreg[2], vreg[3] };
                #pragma unroll
                for (int mf = 0; mf < 2; mf++) {
                    mma16(o[mf][nf2 * 2],     pf[kb2][mf], b0);
                    mma16(o[mf][nf2 * 2 + 1], pf[kb2][mf], b1);
                }
            }
        }
        __syncthreads();
        buf ^= 1;
    }

    uint32_t* Ou = (uint32_t*)O;
    #pragma unroll
    for (int mf = 0; mf < 2; mf++) {
        float l0 = lr[mf][0], l1 = lr[mf][1];
        l0 += __shfl_xor_sync(0xffffffffu, l0, 1);
        l0 += __shfl_xor_sync(0xffffffffu, l0, 2);
        l1 += __shfl_xor_sync(0xffffffffu, l1, 1);
        l1 += __shfl_xor_sync(0xffffffffu, l1, 2);
        float inv0 = 1.f / l0, inv1 = 1.f / l1;
        int r = qb + warp * 32 + mf * 16 + g4;
        size_t ob0 = (size_t)r * (MIDW / 2) + (hoff >> 1);
        size_t ob1 = ob0 + 8 * (MIDW / 2);
        #pragma unroll
        for (int nf = 0; nf < 8; nf++) {
            int ci = nf * 4 + t4;
            Ou[ob0 + ci] = packh(o[mf][nf][0] * inv0, o[mf][nf][1] * inv0);
            Ou[ob1 + ci] = packh(o[mf][nf][2] * inv1, o[mf][nf][3] * inv1);
        }
    }
}

// ---------------------------------------------------------------------------
// Launch
// ---------------------------------------------------------------------------
extern "C" void kernel_launch(void* const* d_in, const int* in_sizes, int n_in,
                              void* d_out, int out_size) {
    const float* x      = (const float*)d_in[0];
    const float* ctx    = (const float*)d_in[1];
    const float* sa_ng  = (const float*)d_in[2];
    const float* sa_nb  = (const float*)d_in[3];
    const float* sa_ncg = (const float*)d_in[4];
    const float* sa_ncb = (const float*)d_in[5];
    const float* sa_wq  = (const float*)d_in[6];
    const float* sa_wkv = (const float*)d_in[7];
    const float* sa_wo  = (const float*)d_in[8];
    const float* sa_bo  = (const float*)d_in[9];
    const float* ca_ng  = (const float*)d_in[10];
    const float* ca_nb  = (const float*)d_in[11];
    const float* ca_ncg = (const float*)d_in[12];
    const float* ca_ncb = (const float*)d_in[13];
    const float* ca_wq  = (const float*)d_in[14];
    const float* ca_wkv = (const float*)d_in[15];
    const float* ca_wo  = (const float*)d_in[16];
    const float* ca_bo  = (const float*)d_in[17];
    float* out = (float*)d_out;

    __half *xn, *cx, *q, *kv, *ao, *wt;
    float *nb, *nbp;
    cudaGetSymbolAddress((void**)&xn, g_xn);
    cudaGetSymbolAddress((void**)&cx, g_cx);
    cudaGetSymbolAddress((void**)&q,  g_q);
    cudaGetSymbolAddress((void**)&kv, g_kv);
    cudaGetSymbolAddress((void**)&ao, g_ao);
    cudaGetSymbolAddress((void**)&wt, g_wt);
    cudaGetSymbolAddress((void**)&nb, g_nb);
    cudaGetSymbolAddress((void**)&nbp, g_nbp);

    static bool inited = false;
    static cudaStream_t s1, s2;
    static cudaEvent_t eFork, eW1, eW2, eC, eB1, eF1, eKV2;
    if (!inited) {
        cudaStreamCreateWithFlags(&s1, cudaStreamNonBlocking);
        cudaStreamCreateWithFlags(&s2, cudaStreamNonBlocking);
        cudaEventCreateWithFlags(&eFork, cudaEventDisableTiming);
        cudaEventCreateWithFlags(&eW1, cudaEventDisableTiming);
        cudaEventCreateWithFlags(&eW2, cudaEventDisableTiming);
        cudaEventCreateWithFlags(&eC,  cudaEventDisableTiming);
        cudaEventCreateWithFlags(&eB1, cudaEventDisableTiming);
        cudaEventCreateWithFlags(&eF1, cudaEventDisableTiming);
        cudaEventCreateWithFlags(&eKV2, cudaEventDisableTiming);
        cudaFuncSetAttribute(gemm_fp16, cudaFuncAttributeMaxDynamicSharedMemorySize, GEMM_SMEM);
        cudaFuncSetAttribute(gemm_qkv,  cudaFuncAttributeMaxDynamicSharedMemorySize, GEMM_SMEM);
        cudaFuncSetAttribute(flash_fp16, cudaFuncAttributeMaxDynamicSharedMemorySize, FL_SMEM);
        inited = true;
    }

    dim3 tb(32, 8);

    cudaEventRecord(eFork, 0);
    cudaStreamWaitEvent(s1, eFork, 0);
    cudaStreamWaitEvent(s2, eFork, 0);

    // Phase A: sa bias vectors FIRST on s2 (off critical path, ~10 us total)
    bvec_partial<<<dim3(MIDW/64, 8), 256, 0, s2>>>(sa_nb, sa_wq, nbp, FF, MIDW, QK_SCALE);
    bvec_combine<<<2, 256, 0, s2>>>(nbp, nb + NB_SA, MIDW);
    bvec_partial<<<dim3(2*MIDW/64, 8), 256, 0, s2>>>(sa_ncb, sa_wkv, nbp, FF, 2*MIDW, 1.f);
    bvec_combine<<<4, 256, 0, s2>>>(nbp, nb + NB_SA + 512, 2*MIDW);
    cudaEventRecord(eB1, s2);

    // plain LN(x) on s0 | sa weight prep on s1
    ln_plain<<<ROWS, 256>>>(x, xn, FF);

    wtrans_kernel<<<dim3(MIDW/32, FF/32),   tb, 0, s1>>>(sa_wq,  wt + OFF_SA_WQ,  FF, MIDW, sa_ng, QK_SCALE);
    wtrans_kernel<<<dim3(2*MIDW/32, FF/32), tb, 0, s1>>>(sa_wkv, wt + OFF_SA_WKV, FF, 2*MIDW, sa_ncg, 1.f);
    cudaEventRecord(eW1, s1);

    // Phase B: merged QKV gemm (768 CTAs) on s0
    cudaStreamWaitEvent(0, eW1, 0);
    cudaStreamWaitEvent(0, eB1, 0);
    gemm_qkv<<<dim3(1536/128, ROWS/128), 128, GEMM_SMEM>>>(
        xn, wt + OFF_SA_WQ, q, kv, ROWS, FF, nb + NB_SA);

    // Phase C: flash-sa on s0
    flash_fp16<<<dim3(NQ/128, BB*HH), 128, FL_SMEM>>>(q, kv, ao, NQ);
    cudaEventRecord(eF1, 0);

    // overlap flash: remaining weight prep on s1; ca biases + ctx LN on s2
    wtrans_kernel<<<dim3(FF/32, MIDW/32),   tb, 0, s1>>>(sa_wo,  wt + OFF_SA_WO,  MIDW, FF, nullptr, 1.f);
    wtrans_kernel<<<dim3(MIDW/32, FF/32),   tb, 0, s1>>>(ca_wq,  wt + OFF_CA_WQ,  FF, MIDW, ca_ng, QK_SCALE);
    wtrans_kernel<<<dim3(2*MIDW/32, CFF/32),tb, 0, s1>>>(ca_wkv, wt + OFF_CA_WKV, CFF, 2*MIDW, ca_ncg, 1.f);
    wtrans_kernel<<<dim3(FF/32, MIDW/32),   tb, 0, s1>>>(ca_wo,  wt + OFF_CA_WO,  MIDW, FF, nullptr, 1.f);
    cudaEventRecord(eW2, s1);

    bvec_partial<<<dim3(MIDW/64, 8), 256, 0, s2>>>(ca_nb, ca_wq, nbp, FF, MIDW, QK_SCALE);
    bvec_combine<<<2, 256, 0, s2>>>(nbp, nb + NB_CA_Q, MIDW);
    bvec_partial<<<dim3(2*MIDW/64, 8), 256, 0, s2>>>(ca_ncb, ca_wkv, nbp, CFF, 2*MIDW, 1.f);
    bvec_combine<<<4, 256, 0, s2>>>(nbp, nb + NB_CA_KV, 2*MIDW);
    ln_plain<<<CROWS, 256, 0, s2>>>(ctx, cx, CFF);
    cudaEventRecord(eC, s2);

    // Phase D: WO-gemm-sa on s0 (fp32 out + bias + residual x)
    cudaStreamWaitEvent(0, eW2, 0);
    gemm_fp16<<<dim3(FF/128, ROWS/128), 128, GEMM_SMEM>>>(
        ao, wt + OFF_SA_WO, out, ROWS, FF, MIDW, sa_bo, x, 0, nullptr);

    // Phase E: LN(out) + Q-gemm-ca on s0
    ln_plain<<<ROWS, 256>>>(out, xn, FF);
    cudaStreamWaitEvent(0, eC, 0);
    gemm_fp16<<<dim3(MIDW/128, ROWS/128), 128, GEMM_SMEM>>>(
        xn, wt + OFF_CA_WQ, q, ROWS, MIDW, FF, nullptr, nullptr, 1, nb + NB_CA_Q);

    // Phase F: KV-gemm-ca on s1 (after flash-sa frees kv; ctx LN + biases done)
    cudaStreamWaitEvent(s1, eF1, 0);
    cudaStreamWaitEvent(s1, eC, 0);
    gemm_fp16<<<dim3(2*MIDW/128, CROWS/128), 128, GEMM_SMEM, s1>>>(
        cx, wt + OFF_CA_WKV, kv, CROWS, 2*MIDW, CFF, nullptr, nullptr, 1, nb + NB_CA_KV);
    cudaEventRecord(eKV2, s1);

    // Phase G: flash-ca + WO-gemm-ca on s0
    cudaStreamWaitEvent(0, eKV2, 0);
    flash_fp16<<<dim3(NQ/128, BB*HH), 128, FL_SMEM>>>(q, kv, ao, 512);
    gemm_fp16<<<dim3(FF/128, ROWS/128), 128, GEMM_SMEM>>>(
        ao, wt + OFF_CA_WO, out, ROWS, FF, MIDW, ca_bo, out, 0, nullptr);
}